// round 7
// baseline (speedup 1.0000x reference)
#include <cuda_runtime.h>
#include <cuda_bf16.h>
#include <cstdint>

#define BATCH 8
#define NT    1024
typedef unsigned long long ull;
typedef unsigned int u32;

// ---------------- scratch (__device__ globals; no allocation allowed) ------
__device__ __align__(16) float g_bufA[BATCH * NT * 256];
__device__ __align__(16) float g_bufB[BATCH * NT * 256];
// scores, laid out [h][b][node]
__device__ __align__(16) float  g_sj [4 * BATCH * NT];
__device__ __align__(16) float  g_Esj[4 * BATCH * NT];
__device__ __align__(16) float  g_Es2[4 * BATCH * NT];
__device__ __align__(16) float4 g_dpk[4 * BATCH * NT];
// pre-transposed bf16-split features [h][b][c=64][node=1024]
__device__ __align__(16) __nv_bfloat16 g_hThi[4 * BATCH * 64 * NT];
__device__ __align__(16) __nv_bfloat16 g_hTlo[4 * BATCH * 64 * NT];
__device__ __align__(16) u32   g_bits[BATCH * NT * (NT / 32)];
__device__ __align__(16) float g_gsum[BATCH * 64];
__device__ __align__(16) float g_z2[BATCH];

// ---------------- helpers --------------------------------------------------
__device__ __forceinline__ uint32_t smem_u32(const void* p) {
    uint32_t a;
    asm("{ .reg .u64 t; cvta.to.shared.u64 t, %1; cvt.u32.u64 %0, t; }" : "=r"(a) : "l"(p));
    return a;
}

__device__ __forceinline__ void ldsm4(u32* r, u32 addr) {
    asm volatile("ldmatrix.sync.aligned.m8n8.x4.shared.b16 {%0,%1,%2,%3}, [%4];"
                 : "=r"(r[0]), "=r"(r[1]), "=r"(r[2]), "=r"(r[3]) : "r"(addr));
}

__device__ __forceinline__ void mma16816(float* c, const u32* a, u32 b0, u32 b1) {
    asm volatile(
        "mma.sync.aligned.m16n8k16.row.col.f32.bf16.bf16.f32 "
        "{%0,%1,%2,%3}, {%4,%5,%6,%7}, {%8,%9}, {%0,%1,%2,%3};"
        : "+f"(c[0]), "+f"(c[1]), "+f"(c[2]), "+f"(c[3])
        : "r"(a[0]), "r"(a[1]), "r"(a[2]), "r"(a[3]), "r"(b0), "r"(b1));
}

__device__ __forceinline__ float edgef(float s, float Es, float Es2, float4 dp, u32 bit) {
    float e = (s + dp.x > 0.f) ? Es * dp.y : Es2 * dp.z;
    return bit ? e : 0.f;
}

// pack two fp32 into bf16x2 (lower = ex, upper = ey) in one cvt
__device__ __forceinline__ u32 packbf2(float ex, float ey) {
    u32 r;
    asm("cvt.rn.bf16x2.f32 %0, %1, %2;" : "=r"(r) : "f"(ey), "f"(ex));
    return r;
}

// sum of the two bf16 values in a packed word, as fp32 (exact widening)
__device__ __forceinline__ float sum2bf(u32 p) {
    float a = __uint_as_float(p << 16);
    float b = __uint_as_float(p & 0xffff0000u);
    return a + b;
}

// hi/lo bf16 split of a pair, packed
__device__ __forceinline__ void split2(float x0, float x1, u32& hi, u32& lo) {
    hi = packbf2(x0, x1);
    float r0 = x0 - __uint_as_float(hi << 16);
    float r1 = x1 - __uint_as_float(hi & 0xffff0000u);
    lo = packbf2(r0, r1);
}

// ---------------- adj bit packing (with self loops) ------------------------
__global__ void pack_adj_kernel(const int* __restrict__ adj, u32* __restrict__ bits) {
    int row = blockIdx.x;                 // b*NT + i
    int lane = threadIdx.x;               // 32 threads
    int i = row & (NT - 1);
    const int* arow = adj + (size_t)row * NT;
    for (int w = 0; w < 32; w++) {
        int j = w * 32 + lane;
        int v = arow[j];
        unsigned m = __ballot_sync(0xffffffffu, (v > 0) || (j == i));
        if (lane == 0) bits[row * 32 + w] = m;
    }
}

// ---------------- fused feature GEMM + scores + bf16-split transpose -------
// Y = X[M,K] @ W[H*64,K]^T, block covers 128 rows x one head (64 cols).
// Epilogue (no f32 feature write at all):
//   - s,d per row via shfl reduction, exp factors to score arrays
//   - bf16 hi/lo split written transposed to [h][b][c][node]
__global__ __launch_bounds__(256) void gemm_fused(
    const float* __restrict__ X, const float* __restrict__ W,
    const float* __restrict__ a_src, const float* __restrict__ a_dst,
    float* __restrict__ sj, float* __restrict__ Esj, float* __restrict__ Es2j,
    float4* __restrict__ dpk,
    __nv_bfloat16* __restrict__ hhi, __nv_bfloat16* __restrict__ hlo,
    int K)
{
    __shared__ float Xs[128][16];
    __shared__ float Ws[64][17];
    int tid = threadIdx.x;
    const int h = blockIdx.y;
    int m0 = blockIdx.x * 128, n0 = h * 64;
    int tx = tid & 15;
    int ty = tid >> 4;
    float acc[8][4];
#pragma unroll
    for (int r = 0; r < 8; r++)
#pragma unroll
        for (int c = 0; c < 4; c++) acc[r][c] = 0.f;

    for (int k0 = 0; k0 < K; k0 += 16) {
#pragma unroll
        for (int l = 0; l < 2; l++) {
            int f = tid + l * 256;
            int row = f >> 2;
            int kc = (f & 3) * 4;
            float4 v = *(const float4*)&X[(size_t)(m0 + row) * K + k0 + kc];
            Xs[row][kc] = v.x; Xs[row][kc + 1] = v.y;
            Xs[row][kc + 2] = v.z; Xs[row][kc + 3] = v.w;
        }
        {
            int row = tid >> 2;
            int kc = (tid & 3) * 4;
            float4 v = *(const float4*)&W[(size_t)(n0 + row) * K + k0 + kc];
            Ws[row][kc] = v.x; Ws[row][kc + 1] = v.y;
            Ws[row][kc + 2] = v.z; Ws[row][kc + 3] = v.w;
        }
        __syncthreads();
#pragma unroll
        for (int kk = 0; kk < 16; kk++) {
            float a[8], bb[4];
#pragma unroll
            for (int r = 0; r < 8; r++) a[r] = Xs[ty * 8 + r][kk];
#pragma unroll
            for (int c = 0; c < 4; c++) bb[c] = Ws[tx * 4 + c][kk];
#pragma unroll
            for (int r = 0; r < 8; r++)
#pragma unroll
                for (int c = 0; c < 4; c++) acc[r][c] += a[r] * bb[c];
        }
        __syncthreads();
    }

    // ---- epilogue 1: attention scores ----
    float as_[4], ad_[4];
#pragma unroll
    for (int c = 0; c < 4; c++) {
        as_[c] = __ldg(a_src + h * 64 + tx * 4 + c);
        ad_[c] = __ldg(a_dst + h * 64 + tx * 4 + c);
    }
    float sv[8], dv[8];
#pragma unroll
    for (int r = 0; r < 8; r++) {
        sv[r] = acc[r][0] * as_[0] + acc[r][1] * as_[1]
              + acc[r][2] * as_[2] + acc[r][3] * as_[3];
        dv[r] = acc[r][0] * ad_[0] + acc[r][1] * ad_[1]
              + acc[r][2] * ad_[2] + acc[r][3] * ad_[3];
    }
#pragma unroll
    for (int o = 1; o < 16; o <<= 1) {
#pragma unroll
        for (int r = 0; r < 8; r++) {
            sv[r] += __shfl_xor_sync(0xffffffffu, sv[r], o);
            dv[r] += __shfl_xor_sync(0xffffffffu, dv[r], o);
        }
    }
    if (tx == 0) {
#pragma unroll
        for (int r = 0; r < 8; r++) {
            int m = m0 + ty * 8 + r;
            int idx = h * (BATCH * NT) + m;
            float s = sv[r], d = dv[r];
            sj[idx]   = s;
            Esj[idx]  = __expf(s);
            Es2j[idx] = __expf(0.2f * s);
            dpk[idx]  = make_float4(d, __expf(d), __expf(0.2f * d), 0.f);
        }
    }

    // ---- epilogue 2: bf16 hi/lo split, transposed [h][b][c][node] ----
    const int b = m0 >> 10;
    const int nodebase = (m0 & (NT - 1)) + ty * 8;
#pragma unroll
    for (int c = 0; c < 4; c++) {
        int col = tx * 4 + c;
        u32 hw[4], lw[4];
#pragma unroll
        for (int p = 0; p < 4; p++)
            split2(acc[2 * p][c], acc[2 * p + 1][c], hw[p], lw[p]);
        size_t off = ((size_t)((h * BATCH + b) * 64 + col)) * NT + nodebase;
        *(uint4*)(hhi + off) = make_uint4(hw[0], hw[1], hw[2], hw[3]);
        *(uint4*)(hlo + off) = make_uint4(lw[0], lw[1], lw[2], lw[3]);
    }
}

// ---------------- HMMA aggregation -----------------------------------------
// grid (NT/128, H, B), 256 threads = 8 warps; warp w owns rows w*16..w*16+15.
// D[i,c] = sum_j E[i,j]*h[j,c] via mma.sync bf16.
// E quantized to bf16 (one A pass); B split hi/lo (2 passes).
// Rowsum accumulated from the QUANTIZED bf16 weights so the correlated
// per-row rounding of E cancels exactly in the normalization.
__global__ __launch_bounds__(256) void agg_mma_kernel(
    const __nv_bfloat16* __restrict__ hThi, const __nv_bfloat16* __restrict__ hTlo,
    const float* __restrict__ sjA, const float* __restrict__ EsA,
    const float* __restrict__ Es2A, const float4* __restrict__ dpk,
    const ull* __restrict__ bits64,
    const float* __restrict__ bias, float* __restrict__ xout, int H)
{
    __shared__ __align__(16) __nv_bfloat16 sh_h[2][2][64 * 64]; // [buf][hi/lo]
    __shared__ float sh_sc[2][3][64];                            // [buf][s/Es/Es2]

    const int tid = threadIdx.x;
    const int w = tid >> 5, l = tid & 31;
    const int b = blockIdx.z, h = blockIdx.y;
    const int i0 = blockIdx.x * 128;
    const int hb = h * BATCH + b;
    const int fs = H * 64;

    // row pair this thread accumulates (within 128-row strip)
    const int r0 = w * 16 + (l >> 2);
    const int r1 = r0 + 8;
    const float4 dp0 = dpk[hb * NT + i0 + r0];
    const float4 dp1 = dpk[hb * NT + i0 + r1];
    const ull* mrow0 = bits64 + (size_t)(b * NT + i0 + r0) * 16;
    const ull* mrow1 = bits64 + (size_t)(b * NT + i0 + r1) * 16;

    const float* sjp = sjA + hb * NT;
    const float* Esp = EsA + hb * NT;
    const float* Fsp = Es2A + hb * NT;
    const __nv_bfloat16* hhp = hThi + (size_t)hb * 64 * NT;
    const __nv_bfloat16* hlp = hTlo + (size_t)hb * 64 * NT;

    // h-tile staging mapping: thread handles chunks tid and tid+256 (16B each)
    const int c0 = tid >> 3, jc = tid & 7;
    auto swz = [](u32 off) { return off ^ ((off >> 3) & 0x70); };
    const u32 st0 = swz((u32)(c0 * 128 + jc * 16));
    const u32 st1 = swz((u32)((c0 + 32) * 128 + jc * 16));
    // score staging
    const float* scsrc = (tid < 64) ? sjp : (tid < 128 ? Esp : Fsp);
    const int scidx = tid & 63;

    float acc[8][4];
#pragma unroll
    for (int ng = 0; ng < 8; ng++)
#pragma unroll
        for (int r = 0; r < 4; r++) acc[ng][r] = 0.f;
    float rs0 = 0.f, rs1 = 0.f;

    uint4 pvh0, pvh1, pvl0, pvl1;
    float psc = 0.f;

    auto ldg_tile = [&](int t) {
        int j0 = t * 64;
        pvh0 = *(const uint4*)(hhp + (size_t)c0 * NT + j0 + jc * 8);
        pvh1 = *(const uint4*)(hhp + (size_t)(c0 + 32) * NT + j0 + jc * 8);
        pvl0 = *(const uint4*)(hlp + (size_t)c0 * NT + j0 + jc * 8);
        pvl1 = *(const uint4*)(hlp + (size_t)(c0 + 32) * NT + j0 + jc * 8);
        if (tid < 192) psc = scsrc[j0 + scidx];
    };

    ldg_tile(0);

    const u32 su_hi[2] = { smem_u32(sh_h[0][0]), smem_u32(sh_h[1][0]) };
    const u32 su_lo[2] = { smem_u32(sh_h[0][1]), smem_u32(sh_h[1][1]) };

    for (int t = 0; t < 16; t++) {
        int buf = t & 1;
        // stage
        *(uint4*)((char*)sh_h[buf][0] + st0) = pvh0;
        *(uint4*)((char*)sh_h[buf][0] + st1) = pvh1;
        *(uint4*)((char*)sh_h[buf][1] + st0) = pvl0;
        *(uint4*)((char*)sh_h[buf][1] + st1) = pvl1;
        if (tid < 192) sh_sc[buf][tid >> 6][scidx] = psc;
        __syncthreads();
        if (t < 15) ldg_tile(t + 1);

        const float* scS = sh_sc[buf][0];
        const float* scE = sh_sc[buf][1];
        const float* scF = sh_sc[buf][2];
        const ull m0 = mrow0[t];
        const ull m1 = mrow1[t];

#pragma unroll
        for (int q = 0; q < 4; q++) {
            const int jA = q * 16 + 2 * (l & 3);
            float s0 = scS[jA], s1 = scS[jA + 1], s2 = scS[jA + 8], s3 = scS[jA + 9];
            float E0 = scE[jA], E1 = scE[jA + 1], E2 = scE[jA + 8], E3 = scE[jA + 9];
            float F0 = scF[jA], F1 = scF[jA + 1], F2 = scF[jA + 8], F3 = scF[jA + 9];

            u32 ahi[4];
            // row r0
            {
                float eA = edgef(s0, E0, F0, dp0, (u32)(m0 >> jA) & 1u);
                float eB = edgef(s1, E1, F1, dp0, (u32)(m0 >> (jA + 1)) & 1u);
                float eC = edgef(s2, E2, F2, dp0, (u32)(m0 >> (jA + 8)) & 1u);
                float eD = edgef(s3, E3, F3, dp0, (u32)(m0 >> (jA + 9)) & 1u);
                ahi[0] = packbf2(eA, eB);
                ahi[2] = packbf2(eC, eD);
                rs0 += sum2bf(ahi[0]) + sum2bf(ahi[2]);
            }
            // row r1
            {
                float eA = edgef(s0, E0, F0, dp1, (u32)(m1 >> jA) & 1u);
                float eB = edgef(s1, E1, F1, dp1, (u32)(m1 >> (jA + 1)) & 1u);
                float eC = edgef(s2, E2, F2, dp1, (u32)(m1 >> (jA + 8)) & 1u);
                float eD = edgef(s3, E3, F3, dp1, (u32)(m1 >> (jA + 9)) & 1u);
                ahi[1] = packbf2(eA, eB);
                ahi[3] = packbf2(eC, eD);
                rs1 += sum2bf(ahi[1]) + sum2bf(ahi[3]);
            }

            // B fragments via ldmatrix (layout [n][k], k-contiguous, SW swizzled)
            u32 bh[16], bl[16];
            const int sub = l >> 3;
            const int brow = (l & 7) + ((sub >> 1) << 3);
            const int bchunk = 2 * q + (sub & 1);
#pragma unroll
            for (int g = 0; g < 4; g++) {
                u32 off = swz((u32)((g * 16 + brow) * 128 + bchunk * 16));
                ldsm4(bh + g * 4, su_hi[buf] + off);
                ldsm4(bl + g * 4, su_lo[buf] + off);
            }
#pragma unroll
            for (int g = 0; g < 4; g++) {
#pragma unroll
                for (int m = 0; m < 2; m++) {
                    int ng = g * 2 + m;
                    u32 h0 = bh[g * 4 + 2 * m], h1 = bh[g * 4 + 2 * m + 1];
                    u32 l0 = bl[g * 4 + 2 * m], l1 = bl[g * 4 + 2 * m + 1];
                    mma16816(acc[ng], ahi, h0, h1);
                    mma16816(acc[ng], ahi, l0, l1);
                }
            }
        }
        __syncthreads();
    }

    // rowsum reduce across the 4 lanes that share a row
    rs0 += __shfl_xor_sync(0xffffffffu, rs0, 1);
    rs0 += __shfl_xor_sync(0xffffffffu, rs0, 2);
    rs1 += __shfl_xor_sync(0xffffffffu, rs1, 1);
    rs1 += __shfl_xor_sync(0xffffffffu, rs1, 2);
    float rinv0 = 1.0f / rs0;
    float rinv1 = 1.0f / rs1;

    float* orow0 = xout + (size_t)(b * NT + i0 + r0) * fs + h * 64;
    float* orow1 = xout + (size_t)(b * NT + i0 + r1) * fs + h * 64;
#pragma unroll
    for (int ng = 0; ng < 8; ng++) {
        int col = ng * 8 + 2 * (l & 3);
        float2 bb = *(const float2*)(bias + h * 64 + col);
        float2 o0, o1;
        o0.x = fmaxf(acc[ng][0] * rinv0 + bb.x, 0.f);
        o0.y = fmaxf(acc[ng][1] * rinv0 + bb.y, 0.f);
        o1.x = fmaxf(acc[ng][2] * rinv1 + bb.x, 0.f);
        o1.y = fmaxf(acc[ng][3] * rinv1 + bb.y, 0.f);
        *(float2*)(orow0 + col) = o0;
        *(float2*)(orow1 + col) = o1;
    }
}

// ---------------- readout --------------------------------------------------
__global__ void gsum_kernel(const float* __restrict__ x, float* __restrict__ g) {
    int b = blockIdx.x;
    int tid = threadIdx.x;
    int c = tid & 63, nq = tid >> 6;
    float acc = 0.f;
    for (int n = nq; n < NT; n += 4) acc += x[((size_t)b * NT + n) * 64 + c];
    __shared__ float sm[256];
    sm[tid] = acc;
    __syncthreads();
    if (tid < 64) g[b * 64 + tid] = sm[tid] + sm[64 + tid] + sm[128 + tid] + sm[192 + tid];
}

__global__ void z2_kernel(const float* __restrict__ g, const float* __restrict__ wg,
                          const float* __restrict__ bg, const float* __restrict__ wv,
                          float* __restrict__ z2) {
    int b = blockIdx.x;
    int c = threadIdx.x;
    float acc = bg[c];
    for (int k = 0; k < 64; k++) acc += g[b * 64 + k] * wg[c * 64 + k];
    float y = fmaxf(acc, 0.f) * wv[64 + c];
    __shared__ float sm[64];
    sm[c] = y;
    __syncthreads();
    if (c == 0) {
        float t = 0.f;
        for (int k = 0; k < 64; k++) t += sm[k];
        z2[b] = t;
    }
}

__global__ __launch_bounds__(256) void final_kernel(
    const float* __restrict__ x,
    const float* __restrict__ wn, const float* __restrict__ bn,
    const float* __restrict__ wv, const float* __restrict__ bv,
    const float* __restrict__ z2, float* __restrict__ out)
{
    __shared__ float wns[64][65];
    __shared__ float bns[64], wvs[64];
    int tid = threadIdx.x;
#pragma unroll
    for (int l = 0; l < 16; l++) {
        int f = tid + l * 256;
        wns[f >> 6][f & 63] = wn[f];
    }
    if (tid < 64) { bns[tid] = bn[tid]; wvs[tid] = wv[tid]; }
    __syncthreads();

    int row = blockIdx.x * 64 + (tid >> 2);
    int q = tid & 3;
    float xr[64];
#pragma unroll
    for (int k = 0; k < 64; k++) xr[k] = x[(size_t)row * 64 + k];
    float y = 0.f;
    for (int c16 = 0; c16 < 16; c16++) {
        int c = q * 16 + c16;
        float acc = bns[c];
#pragma unroll
        for (int k = 0; k < 64; k++) acc += xr[k] * wns[c][k];
        y += fmaxf(acc, 0.f) * wvs[c];
    }
    y += __shfl_xor_sync(0xffffffffu, y, 1);
    y += __shfl_xor_sync(0xffffffffu, y, 2);
    if (q == 0) out[row] = y + z2[row >> 10] + bv[0];
}

// ---------------- launch ----------------------------------------------------
extern "C" void kernel_launch(void* const* d_in, const int* in_sizes, int n_in,
                              void* d_out, int out_size)
{
    const float* xin = (const float*)d_in[0];
    const int*   adj = (const int*)d_in[1];
    const float* w1  = (const float*)d_in[2];
    const float* as1 = (const float*)d_in[3];
    const float* ad1 = (const float*)d_in[4];
    const float* b1  = (const float*)d_in[5];
    const float* w2  = (const float*)d_in[6];
    const float* as2 = (const float*)d_in[7];
    const float* ad2 = (const float*)d_in[8];
    const float* b2  = (const float*)d_in[9];
    const float* w3  = (const float*)d_in[10];
    const float* as3 = (const float*)d_in[11];
    const float* ad3 = (const float*)d_in[12];
    const float* b3  = (const float*)d_in[13];
    const float* wn  = (const float*)d_in[14];
    const float* bn  = (const float*)d_in[15];
    const float* wg  = (const float*)d_in[16];
    const float* bg  = (const float*)d_in[17];
    const float* wv  = (const float*)d_in[18];
    const float* bv  = (const float*)d_in[19];
    float* out = (float*)d_out;

    float *bufA, *bufB, *sA, *EsA, *Es2A, *gsm, *z2p;
    float4* dpk;
    __nv_bfloat16 *hhi, *hlo;
    u32* bits;
    cudaGetSymbolAddress((void**)&bufA, g_bufA);
    cudaGetSymbolAddress((void**)&bufB, g_bufB);
    cudaGetSymbolAddress((void**)&sA,   g_sj);
    cudaGetSymbolAddress((void**)&EsA,  g_Esj);
    cudaGetSymbolAddress((void**)&Es2A, g_Es2);
    cudaGetSymbolAddress((void**)&dpk,  g_dpk);
    cudaGetSymbolAddress((void**)&hhi,  g_hThi);
    cudaGetSymbolAddress((void**)&hlo,  g_hTlo);
    cudaGetSymbolAddress((void**)&bits, g_bits);
    cudaGetSymbolAddress((void**)&gsm,  g_gsum);
    cudaGetSymbolAddress((void**)&z2p,  g_z2);

    const int M = BATCH * NT;
    const ull* bits64 = (const ull*)bits;

    pack_adj_kernel<<<M, 32>>>(adj, bits);

    // layer 1: 64 -> 4x64 (gemm + scores + split-transpose fused)
    gemm_fused<<<dim3(M / 128, 4), 256>>>(xin, w1, as1, ad1,
                                          sA, EsA, Es2A, dpk, hhi, hlo, 64);
    agg_mma_kernel<<<dim3(NT / 128, 4, BATCH), 256>>>(
        hhi, hlo, sA, EsA, Es2A, dpk, bits64, b1, bufB, 4);

    // layer 2: 4x64 -> 4x64
    gemm_fused<<<dim3(M / 128, 4), 256>>>(bufB, w2, as2, ad2,
                                          sA, EsA, Es2A, dpk, hhi, hlo, 256);
    agg_mma_kernel<<<dim3(NT / 128, 4, BATCH), 256>>>(
        hhi, hlo, sA, EsA, Es2A, dpk, bits64, b2, bufA, 4);

    // layer 3: 4x64 -> 64 (H=1)
    gemm_fused<<<dim3(M / 128, 1), 256>>>(bufA, w3, as3, ad3,
                                          sA, EsA, Es2A, dpk, hhi, hlo, 256);
    agg_mma_kernel<<<dim3(NT / 128, 1, BATCH), 256>>>(
        hhi, hlo, sA, EsA, Es2A, dpk, bits64, b3, bufB, 1);

    // readout
    gsum_kernel<<<BATCH, 256>>>(bufB, gsm);
    z2_kernel<<<BATCH, 64>>>(gsm, wg, bg, wv, z2p);
    final_kernel<<<M / 64, 256>>>(bufB, wn, bn, wv, bv, z2p, out);
}

// round 8
// speedup vs baseline: 1.6544x; 1.6544x over previous
#include <cuda_runtime.h>
#include <cuda_bf16.h>
#include <cstdint>

#define BATCH 8
#define NT    1024
typedef unsigned long long ull;
typedef unsigned int u32;

// ---------------- scratch (__device__ globals; no allocation allowed) ------
__device__ __align__(16) float g_bufA[BATCH * NT * 256];
__device__ __align__(16) float g_bufB[BATCH * NT * 256];
// scores, laid out [h][b][node]
__device__ __align__(16) float  g_sj [4 * BATCH * NT];
__device__ __align__(16) float  g_Esj[4 * BATCH * NT];
__device__ __align__(16) float  g_Es2[4 * BATCH * NT];
__device__ __align__(16) float4 g_dpk[4 * BATCH * NT];
// pre-transposed bf16-split features [h][b][c=64][node=1024]
__device__ __align__(16) __nv_bfloat16 g_hThi[4 * BATCH * 64 * NT];
__device__ __align__(16) __nv_bfloat16 g_hTlo[4 * BATCH * 64 * NT];
__device__ __align__(16) u32   g_bits[BATCH * NT * (NT / 32)];
__device__ __align__(16) float g_gsum[BATCH * 64];
__device__ __align__(16) float g_z2[BATCH];

// ---------------- helpers --------------------------------------------------
__device__ __forceinline__ uint32_t smem_u32(const void* p) {
    uint32_t a;
    asm("{ .reg .u64 t; cvta.to.shared.u64 t, %1; cvt.u32.u64 %0, t; }" : "=r"(a) : "l"(p));
    return a;
}

__device__ __forceinline__ void ldsm4(u32* r, u32 addr) {
    asm volatile("ldmatrix.sync.aligned.m8n8.x4.shared.b16 {%0,%1,%2,%3}, [%4];"
                 : "=r"(r[0]), "=r"(r[1]), "=r"(r[2]), "=r"(r[3]) : "r"(addr));
}

__device__ __forceinline__ void mma16816(float* c, const u32* a, u32 b0, u32 b1) {
    asm volatile(
        "mma.sync.aligned.m16n8k16.row.col.f32.bf16.bf16.f32 "
        "{%0,%1,%2,%3}, {%4,%5,%6,%7}, {%8,%9}, {%0,%1,%2,%3};"
        : "+f"(c[0]), "+f"(c[1]), "+f"(c[2]), "+f"(c[3])
        : "r"(a[0]), "r"(a[1]), "r"(a[2]), "r"(a[3]), "r"(b0), "r"(b1));
}

__device__ __forceinline__ float edgef(float s, float Es, float Es2, float4 dp, u32 bit) {
    float e = (s + dp.x > 0.f) ? Es * dp.y : Es2 * dp.z;
    return bit ? e : 0.f;
}

// pack two fp32 into bf16x2 (lower = ex, upper = ey) in one cvt
__device__ __forceinline__ u32 packbf2(float ex, float ey) {
    u32 r;
    asm("cvt.rn.bf16x2.f32 %0, %1, %2;" : "=r"(r) : "f"(ey), "f"(ex));
    return r;
}

// sum of the two bf16 values in a packed word, as fp32 (exact widening)
__device__ __forceinline__ float sum2bf(u32 p) {
    float a = __uint_as_float(p << 16);
    float b = __uint_as_float(p & 0xffff0000u);
    return a + b;
}

// hi/lo bf16 split of a pair, packed
__device__ __forceinline__ void split2(float x0, float x1, u32& hi, u32& lo) {
    hi = packbf2(x0, x1);
    float r0 = x0 - __uint_as_float(hi << 16);
    float r1 = x1 - __uint_as_float(hi & 0xffff0000u);
    lo = packbf2(r0, r1);
}

__device__ __forceinline__ u32 swzf(u32 off) { return off ^ ((off >> 3) & 0x70); }

// ---------------- adj bit packing (with self loops) ------------------------
__global__ void pack_adj_kernel(const int* __restrict__ adj, u32* __restrict__ bits) {
    int row = blockIdx.x;                 // b*NT + i
    int lane = threadIdx.x;               // 32 threads
    int i = row & (NT - 1);
    const int* arow = adj + (size_t)row * NT;
    for (int w = 0; w < 32; w++) {
        int j = w * 32 + lane;
        int v = arow[j];
        unsigned m = __ballot_sync(0xffffffffu, (v > 0) || (j == i));
        if (lane == 0) bits[row * 32 + w] = m;
    }
}

// ---------------- HMMA feature GEMM: Y[M,Nc] = X[M,K] @ W[Nc,K]^T ----------
// grid (M/128, Nc/64), 256 threads = 8 warps. X,W split to bf16 hi/lo at
// staging; 3 MMA passes (hi*hi + hi*loW + loX*hi) -> ~1e-5 relative error.
__global__ __launch_bounds__(256) void gemm_mma(
    const float* __restrict__ X, const float* __restrict__ W,
    float* __restrict__ Y, int K, int Nc)
{
    __shared__ __align__(128) __nv_bfloat16 sXh[128 * 64];
    __shared__ __align__(128) __nv_bfloat16 sXl[128 * 64];
    __shared__ __align__(128) __nv_bfloat16 sWh[64 * 64];
    __shared__ __align__(128) __nv_bfloat16 sWl[64 * 64];

    const int tid = threadIdx.x;
    const int w = tid >> 5, l = tid & 31;
    const int m0 = blockIdx.x * 128, n0 = blockIdx.y * 64;

    const u32 uXh = smem_u32(sXh), uXl = smem_u32(sXl);
    const u32 uWh = smem_u32(sWh), uWl = smem_u32(sWl);

    float acc[8][4];
#pragma unroll
    for (int ng = 0; ng < 8; ng++)
#pragma unroll
        for (int r = 0; r < 4; r++) acc[ng][r] = 0.f;

    // A-fragment ldmatrix row address (canonical x4 mapping)
    const int arow = w * 16 + (l & 7) + ((l >> 3) & 1) * 8;
    const int akh  = (l >> 4);
    // B-fragment address pieces (identical scheme to agg's h tiles)
    const int sub = l >> 3;
    const int brow = (l & 7) + ((sub >> 1) << 3);

    for (int k0 = 0; k0 < K; k0 += 64) {
        __syncthreads();   // previous compute done before restage
        // ---- stage X tile (128x64) with inline bf16 split ----
#pragma unroll
        for (int i = 0; i < 4; i++) {
            int c = tid + i * 256;
            int row = c >> 3, kg = c & 7;
            const float* p = X + (size_t)(m0 + row) * K + k0 + kg * 8;
            float4 v0 = *(const float4*)p;
            float4 v1 = *(const float4*)(p + 4);
            u32 h0, h1, h2, h3, l0, l1, l2, l3;
            split2(v0.x, v0.y, h0, l0); split2(v0.z, v0.w, h1, l1);
            split2(v1.x, v1.y, h2, l2); split2(v1.z, v1.w, h3, l3);
            u32 off = swzf((u32)(row * 128 + kg * 16));
            *(uint4*)((char*)sXh + off) = make_uint4(h0, h1, h2, h3);
            *(uint4*)((char*)sXl + off) = make_uint4(l0, l1, l2, l3);
        }
        // ---- stage W tile (64x64) with inline bf16 split ----
#pragma unroll
        for (int i = 0; i < 2; i++) {
            int c = tid + i * 256;
            int row = c >> 3, kg = c & 7;
            const float* p = W + (size_t)(n0 + row) * K + k0 + kg * 8;
            float4 v0 = *(const float4*)p;
            float4 v1 = *(const float4*)(p + 4);
            u32 h0, h1, h2, h3, l0, l1, l2, l3;
            split2(v0.x, v0.y, h0, l0); split2(v0.z, v0.w, h1, l1);
            split2(v1.x, v1.y, h2, l2); split2(v1.z, v1.w, h3, l3);
            u32 off = swzf((u32)(row * 128 + kg * 16));
            *(uint4*)((char*)sWh + off) = make_uint4(h0, h1, h2, h3);
            *(uint4*)((char*)sWl + off) = make_uint4(l0, l1, l2, l3);
        }
        __syncthreads();

        // ---- compute: 4 k16 steps ----
#pragma unroll
        for (int q = 0; q < 4; q++) {
            u32 ah[4], al[4];
            u32 aoff = swzf((u32)(arow * 128 + q * 32 + akh * 16));
            ldsm4(ah, uXh + aoff);
            ldsm4(al, uXl + aoff);
            const int bchunk = 2 * q + (sub & 1);
            u32 bh[16], bl[16];
#pragma unroll
            for (int g = 0; g < 4; g++) {
                u32 off = swzf((u32)((g * 16 + brow) * 128 + bchunk * 16));
                ldsm4(bh + g * 4, uWh + off);
                ldsm4(bl + g * 4, uWl + off);
            }
#pragma unroll
            for (int g = 0; g < 4; g++) {
#pragma unroll
                for (int m = 0; m < 2; m++) {
                    int ng = g * 2 + m;
                    u32 b0 = bh[g * 4 + 2 * m], b1 = bh[g * 4 + 2 * m + 1];
                    u32 c0 = bl[g * 4 + 2 * m], c1 = bl[g * 4 + 2 * m + 1];
                    mma16816(acc[ng], ah, b0, b1);
                    mma16816(acc[ng], ah, c0, c1);
                    mma16816(acc[ng], al, b0, b1);
                }
            }
        }
    }

    // ---- epilogue: plain f32 store ----
    const int r0 = w * 16 + (l >> 2);
    const int r1 = r0 + 8;
    float* y0 = Y + (size_t)(m0 + r0) * Nc + n0;
    float* y1 = Y + (size_t)(m0 + r1) * Nc + n0;
#pragma unroll
    for (int ng = 0; ng < 8; ng++) {
        int col = ng * 8 + 2 * (l & 3);
        *(float2*)(y0 + col) = make_float2(acc[ng][0], acc[ng][1]);
        *(float2*)(y1 + col) = make_float2(acc[ng][2], acc[ng][3]);
    }
}

// ---------------- attention score precompute -------------------------------
// outputs laid out [h][b][node]
__global__ void scores_kernel(
    const float* __restrict__ feat,
    const float* __restrict__ a_src, const float* __restrict__ a_dst,
    float* __restrict__ sj, float* __restrict__ Esj, float* __restrict__ Es2j,
    float4* __restrict__ dpk, int H)
{
    int gtid = blockIdx.x * blockDim.x + threadIdx.x;
    int wid = gtid >> 5;
    int lane = threadIdx.x & 31;
    if (wid >= BATCH * NT) return;
    const float* frow = feat + (size_t)wid * H * 64;
    for (int h = 0; h < H; h++) {
        float f0 = frow[h * 64 + lane];
        float f1 = frow[h * 64 + 32 + lane];
        float s = f0 * a_src[h * 64 + lane] + f1 * a_src[h * 64 + 32 + lane];
        float d = f0 * a_dst[h * 64 + lane] + f1 * a_dst[h * 64 + 32 + lane];
#pragma unroll
        for (int o = 16; o > 0; o >>= 1) {
            s += __shfl_xor_sync(0xffffffffu, s, o);
            d += __shfl_xor_sync(0xffffffffu, d, o);
        }
        if (lane == 0) {
            int idx = h * (BATCH * NT) + wid;
            sj[idx]   = s;
            Esj[idx]  = __expf(s);
            Es2j[idx] = __expf(0.2f * s);
            dpk[idx]  = make_float4(d, __expf(d), __expf(0.2f * d), 0.f);
        }
    }
}

// ---------------- transpose + bf16-split features --------------------------
// feat [b][node][H*64] f32  ->  hThi/hTlo [h][b][c=64][node=NT] bf16
__global__ __launch_bounds__(256) void transpose_kernel(
    const float* __restrict__ feat,
    __nv_bfloat16* __restrict__ hhi, __nv_bfloat16* __restrict__ hlo, int H)
{
    __shared__ float ts[64][65];
    int tid = threadIdx.x;
    int jt = blockIdx.x, h = blockIdx.y, b = blockIdx.z;
    int j0 = jt * 64;
    int fs = H * 64;
    const float* fb = feat + (size_t)(b * NT + j0) * fs + h * 64;
#pragma unroll
    for (int l = 0; l < 4; l++) {
        int f = tid + l * 256;
        int j = f >> 4, c4 = f & 15;
        float4 v = *(const float4*)(fb + (size_t)j * fs + c4 * 4);
        ts[j][c4 * 4] = v.x; ts[j][c4 * 4 + 1] = v.y;
        ts[j][c4 * 4 + 2] = v.z; ts[j][c4 * 4 + 3] = v.w;
    }
    __syncthreads();
    int c = tid >> 2, q = tid & 3;
    size_t gof = ((size_t)((h * BATCH + b) * 64 + c)) * NT + j0 + q * 16;
    u32 hw[8], lw[8];
#pragma unroll
    for (int p = 0; p < 8; p++) {
        float x0 = ts[q * 16 + 2 * p][c];
        float x1 = ts[q * 16 + 2 * p + 1][c];
        split2(x0, x1, hw[p], lw[p]);
    }
    *(uint4*)(hhi + gof)     = make_uint4(hw[0], hw[1], hw[2], hw[3]);
    *(uint4*)(hhi + gof + 8) = make_uint4(hw[4], hw[5], hw[6], hw[7]);
    *(uint4*)(hlo + gof)     = make_uint4(lw[0], lw[1], lw[2], lw[3]);
    *(uint4*)(hlo + gof + 8) = make_uint4(lw[4], lw[5], lw[6], lw[7]);
}

// ---------------- HMMA aggregation -----------------------------------------
// grid (NT/128, H, B), 256 threads = 8 warps; warp w owns rows w*16..w*16+15.
// D[i,c] = sum_j E[i,j]*h[j,c] via mma.sync bf16.
// E quantized to bf16 (one A pass); B split hi/lo (2 passes).
// Rowsum accumulated from the QUANTIZED bf16 weights so the correlated
// per-row rounding of E cancels exactly in the normalization.
__global__ __launch_bounds__(256) void agg_mma_kernel(
    const __nv_bfloat16* __restrict__ hThi, const __nv_bfloat16* __restrict__ hTlo,
    const float* __restrict__ sjA, const float* __restrict__ EsA,
    const float* __restrict__ Es2A, const float4* __restrict__ dpk,
    const ull* __restrict__ bits64,
    const float* __restrict__ bias, float* __restrict__ xout, int H)
{
    __shared__ __align__(16) __nv_bfloat16 sh_h[2][2][64 * 64]; // [buf][hi/lo]
    __shared__ float sh_sc[2][3][64];                            // [buf][s/Es/Es2]

    const int tid = threadIdx.x;
    const int w = tid >> 5, l = tid & 31;
    const int b = blockIdx.z, h = blockIdx.y;
    const int i0 = blockIdx.x * 128;
    const int hb = h * BATCH + b;
    const int fs = H * 64;

    // row pair this thread accumulates (within 128-row strip)
    const int r0 = w * 16 + (l >> 2);
    const int r1 = r0 + 8;
    const float4 dp0 = dpk[hb * NT + i0 + r0];
    const float4 dp1 = dpk[hb * NT + i0 + r1];
    const ull* mrow0 = bits64 + (size_t)(b * NT + i0 + r0) * 16;
    const ull* mrow1 = bits64 + (size_t)(b * NT + i0 + r1) * 16;

    const float* sjp = sjA + hb * NT;
    const float* Esp = EsA + hb * NT;
    const float* Fsp = Es2A + hb * NT;
    const __nv_bfloat16* hhp = hThi + (size_t)hb * 64 * NT;
    const __nv_bfloat16* hlp = hTlo + (size_t)hb * 64 * NT;

    // h-tile staging mapping: thread handles chunks tid and tid+256 (16B each)
    const int c0 = tid >> 3, jc = tid & 7;
    const u32 st0 = swzf((u32)(c0 * 128 + jc * 16));
    const u32 st1 = swzf((u32)((c0 + 32) * 128 + jc * 16));
    // score staging
    const float* scsrc = (tid < 64) ? sjp : (tid < 128 ? Esp : Fsp);
    const int scidx = tid & 63;

    float acc[8][4];
#pragma unroll
    for (int ng = 0; ng < 8; ng++)
#pragma unroll
        for (int r = 0; r < 4; r++) acc[ng][r] = 0.f;
    float rs0 = 0.f, rs1 = 0.f;

    uint4 pvh0, pvh1, pvl0, pvl1;
    float psc = 0.f;

    auto ldg_tile = [&](int t) {
        int j0 = t * 64;
        pvh0 = *(const uint4*)(hhp + (size_t)c0 * NT + j0 + jc * 8);
        pvh1 = *(const uint4*)(hhp + (size_t)(c0 + 32) * NT + j0 + jc * 8);
        pvl0 = *(const uint4*)(hlp + (size_t)c0 * NT + j0 + jc * 8);
        pvl1 = *(const uint4*)(hlp + (size_t)(c0 + 32) * NT + j0 + jc * 8);
        if (tid < 192) psc = scsrc[j0 + scidx];
    };

    ldg_tile(0);

    const u32 su_hi[2] = { smem_u32(sh_h[0][0]), smem_u32(sh_h[1][0]) };
    const u32 su_lo[2] = { smem_u32(sh_h[0][1]), smem_u32(sh_h[1][1]) };

    for (int t = 0; t < 16; t++) {
        int buf = t & 1;
        // stage
        *(uint4*)((char*)sh_h[buf][0] + st0) = pvh0;
        *(uint4*)((char*)sh_h[buf][0] + st1) = pvh1;
        *(uint4*)((char*)sh_h[buf][1] + st0) = pvl0;
        *(uint4*)((char*)sh_h[buf][1] + st1) = pvl1;
        if (tid < 192) sh_sc[buf][tid >> 6][scidx] = psc;
        __syncthreads();
        if (t < 15) ldg_tile(t + 1);

        const float* scS = sh_sc[buf][0];
        const float* scE = sh_sc[buf][1];
        const float* scF = sh_sc[buf][2];
        const ull m0 = mrow0[t];
        const ull m1 = mrow1[t];

#pragma unroll
        for (int q = 0; q < 4; q++) {
            const int jA = q * 16 + 2 * (l & 3);
            float s0 = scS[jA], s1 = scS[jA + 1], s2 = scS[jA + 8], s3 = scS[jA + 9];
            float E0 = scE[jA], E1 = scE[jA + 1], E2 = scE[jA + 8], E3 = scE[jA + 9];
            float F0 = scF[jA], F1 = scF[jA + 1], F2 = scF[jA + 8], F3 = scF[jA + 9];

            u32 ahi[4];
            // row r0
            {
                float eA = edgef(s0, E0, F0, dp0, (u32)(m0 >> jA) & 1u);
                float eB = edgef(s1, E1, F1, dp0, (u32)(m0 >> (jA + 1)) & 1u);
                float eC = edgef(s2, E2, F2, dp0, (u32)(m0 >> (jA + 8)) & 1u);
                float eD = edgef(s3, E3, F3, dp0, (u32)(m0 >> (jA + 9)) & 1u);
                ahi[0] = packbf2(eA, eB);
                ahi[2] = packbf2(eC, eD);
                rs0 += sum2bf(ahi[0]) + sum2bf(ahi[2]);
            }
            // row r1
            {
                float eA = edgef(s0, E0, F0, dp1, (u32)(m1 >> jA) & 1u);
                float eB = edgef(s1, E1, F1, dp1, (u32)(m1 >> (jA + 1)) & 1u);
                float eC = edgef(s2, E2, F2, dp1, (u32)(m1 >> (jA + 8)) & 1u);
                float eD = edgef(s3, E3, F3, dp1, (u32)(m1 >> (jA + 9)) & 1u);
                ahi[1] = packbf2(eA, eB);
                ahi[3] = packbf2(eC, eD);
                rs1 += sum2bf(ahi[1]) + sum2bf(ahi[3]);
            }

            // B fragments via ldmatrix (layout [n][k], k-contiguous, SW swizzled)
            u32 bh[16], bl[16];
            const int sub = l >> 3;
            const int brow = (l & 7) + ((sub >> 1) << 3);
            const int bchunk = 2 * q + (sub & 1);
#pragma unroll
            for (int g = 0; g < 4; g++) {
                u32 off = swzf((u32)((g * 16 + brow) * 128 + bchunk * 16));
                ldsm4(bh + g * 4, su_hi[buf] + off);
                ldsm4(bl + g * 4, su_lo[buf] + off);
            }
#pragma unroll
            for (int g = 0; g < 4; g++) {
#pragma unroll
                for (int m = 0; m < 2; m++) {
                    int ng = g * 2 + m;
                    u32 h0 = bh[g * 4 + 2 * m], h1 = bh[g * 4 + 2 * m + 1];
                    u32 l0 = bl[g * 4 + 2 * m], l1 = bl[g * 4 + 2 * m + 1];
                    mma16816(acc[ng], ahi, h0, h1);
                    mma16816(acc[ng], ahi, l0, l1);
                }
            }
        }
        __syncthreads();
    }

    // rowsum reduce across the 4 lanes that share a row
    rs0 += __shfl_xor_sync(0xffffffffu, rs0, 1);
    rs0 += __shfl_xor_sync(0xffffffffu, rs0, 2);
    rs1 += __shfl_xor_sync(0xffffffffu, rs1, 1);
    rs1 += __shfl_xor_sync(0xffffffffu, rs1, 2);
    float rinv0 = 1.0f / rs0;
    float rinv1 = 1.0f / rs1;

    float* orow0 = xout + (size_t)(b * NT + i0 + r0) * fs + h * 64;
    float* orow1 = xout + (size_t)(b * NT + i0 + r1) * fs + h * 64;
#pragma unroll
    for (int ng = 0; ng < 8; ng++) {
        int col = ng * 8 + 2 * (l & 3);
        float2 bb = *(const float2*)(bias + h * 64 + col);
        float2 o0, o1;
        o0.x = fmaxf(acc[ng][0] * rinv0 + bb.x, 0.f);
        o0.y = fmaxf(acc[ng][1] * rinv0 + bb.y, 0.f);
        o1.x = fmaxf(acc[ng][2] * rinv1 + bb.x, 0.f);
        o1.y = fmaxf(acc[ng][3] * rinv1 + bb.y, 0.f);
        *(float2*)(orow0 + col) = o0;
        *(float2*)(orow1 + col) = o1;
    }
}

// ---------------- readout --------------------------------------------------
__global__ void gsum_kernel(const float* __restrict__ x, float* __restrict__ g) {
    int b = blockIdx.x;
    int tid = threadIdx.x;
    int c = tid & 63, nq = tid >> 6;
    float acc = 0.f;
    for (int n = nq; n < NT; n += 4) acc += x[((size_t)b * NT + n) * 64 + c];
    __shared__ float sm[256];
    sm[tid] = acc;
    __syncthreads();
    if (tid < 64) g[b * 64 + tid] = sm[tid] + sm[64 + tid] + sm[128 + tid] + sm[192 + tid];
}

__global__ void z2_kernel(const float* __restrict__ g, const float* __restrict__ wg,
                          const float* __restrict__ bg, const float* __restrict__ wv,
                          float* __restrict__ z2) {
    int b = blockIdx.x;
    int c = threadIdx.x;
    float acc = bg[c];
    for (int k = 0; k < 64; k++) acc += g[b * 64 + k] * wg[c * 64 + k];
    float y = fmaxf(acc, 0.f) * wv[64 + c];
    __shared__ float sm[64];
    sm[c] = y;
    __syncthreads();
    if (c == 0) {
        float t = 0.f;
        for (int k = 0; k < 64; k++) t += sm[k];
        z2[b] = t;
    }
}

__global__ __launch_bounds__(256) void final_kernel(
    const float* __restrict__ x,
    const float* __restrict__ wn, const float* __restrict__ bn,
    const float* __restrict__ wv, const float* __restrict__ bv,
    const float* __restrict__ z2, float* __restrict__ out)
{
    __shared__ float wns[64][65];
    __shared__ float bns[64], wvs[64];
    int tid = threadIdx.x;
#pragma unroll
    for (int l = 0; l < 16; l++) {
        int f = tid + l * 256;
        wns[f >> 6][f & 63] = wn[f];
    }
    if (tid < 64) { bns[tid] = bn[tid]; wvs[tid] = wv[tid]; }
    __syncthreads();

    int row = blockIdx.x * 64 + (tid >> 2);
    int q = tid & 3;
    float xr[64];
#pragma unroll
    for (int k = 0; k < 64; k++) xr[k] = x[(size_t)row * 64 + k];
    float y = 0.f;
    for (int c16 = 0; c16 < 16; c16++) {
        int c = q * 16 + c16;
        float acc = bns[c];
#pragma unroll
        for (int k = 0; k < 64; k++) acc += xr[k] * wns[c][k];
        y += fmaxf(acc, 0.f) * wvs[c];
    }
    y += __shfl_xor_sync(0xffffffffu, y, 1);
    y += __shfl_xor_sync(0xffffffffu, y, 2);
    if (q == 0) out[row] = y + z2[row >> 10] + bv[0];
}

// ---------------- launch ----------------------------------------------------
extern "C" void kernel_launch(void* const* d_in, const int* in_sizes, int n_in,
                              void* d_out, int out_size)
{
    const float* xin = (const float*)d_in[0];
    const int*   adj = (const int*)d_in[1];
    const float* w1  = (const float*)d_in[2];
    const float* as1 = (const float*)d_in[3];
    const float* ad1 = (const float*)d_in[4];
    const float* b1  = (const float*)d_in[5];
    const float* w2  = (const float*)d_in[6];
    const float* as2 = (const float*)d_in[7];
    const float* ad2 = (const float*)d_in[8];
    const float* b2  = (const float*)d_in[9];
    const float* w3  = (const float*)d_in[10];
    const float* as3 = (const float*)d_in[11];
    const float* ad3 = (const float*)d_in[12];
    const float* b3  = (const float*)d_in[13];
    const float* wn  = (const float*)d_in[14];
    const float* bn  = (const float*)d_in[15];
    const float* wg  = (const float*)d_in[16];
    const float* bg  = (const float*)d_in[17];
    const float* wv  = (const float*)d_in[18];
    const float* bv  = (const float*)d_in[19];
    float* out = (float*)d_out;

    float *bufA, *bufB, *sA, *EsA, *Es2A, *gsm, *z2p;
    float4* dpk;
    __nv_bfloat16 *hhi, *hlo;
    u32* bits;
    cudaGetSymbolAddress((void**)&bufA, g_bufA);
    cudaGetSymbolAddress((void**)&bufB, g_bufB);
    cudaGetSymbolAddress((void**)&sA,   g_sj);
    cudaGetSymbolAddress((void**)&EsA,  g_Esj);
    cudaGetSymbolAddress((void**)&Es2A, g_Es2);
    cudaGetSymbolAddress((void**)&dpk,  g_dpk);
    cudaGetSymbolAddress((void**)&hhi,  g_hThi);
    cudaGetSymbolAddress((void**)&hlo,  g_hTlo);
    cudaGetSymbolAddress((void**)&bits, g_bits);
    cudaGetSymbolAddress((void**)&gsm,  g_gsum);
    cudaGetSymbolAddress((void**)&z2p,  g_z2);

    const int M = BATCH * NT;
    const ull* bits64 = (const ull*)bits;

    pack_adj_kernel<<<M, 32>>>(adj, bits);

    // layer 1: 64 -> 4x64
    gemm_mma<<<dim3(M / 128, 4), 256>>>(xin, w1, bufA, 64, 256);
    scores_kernel<<<(M * 32) / 256, 256>>>(bufA, as1, ad1, sA, EsA, Es2A, dpk, 4);
    transpose_kernel<<<dim3(16, 4, BATCH), 256>>>(bufA, hhi, hlo, 4);
    agg_mma_kernel<<<dim3(NT / 128, 4, BATCH), 256>>>(
        hhi, hlo, sA, EsA, Es2A, dpk, bits64, b1, bufB, 4);

    // layer 2: 4x64 -> 4x64
    gemm_mma<<<dim3(M / 128, 4), 256>>>(bufB, w2, bufA, 256, 256);
    scores_kernel<<<(M * 32) / 256, 256>>>(bufA, as2, ad2, sA, EsA, Es2A, dpk, 4);
    transpose_kernel<<<dim3(16, 4, BATCH), 256>>>(bufA, hhi, hlo, 4);
    agg_mma_kernel<<<dim3(NT / 128, 4, BATCH), 256>>>(
        hhi, hlo, sA, EsA, Es2A, dpk, bits64, b2, bufB, 4);

    // layer 3: 4x64 -> 64 (H=1)
    gemm_mma<<<dim3(M / 128, 1), 256>>>(bufB, w3, bufA, 256, 64);
    scores_kernel<<<(M * 32) / 256, 256>>>(bufA, as3, ad3, sA, EsA, Es2A, dpk, 1);
    transpose_kernel<<<dim3(16, 1, BATCH), 256>>>(bufA, hhi, hlo, 1);
    agg_mma_kernel<<<dim3(NT / 128, 1, BATCH), 256>>>(
        hhi, hlo, sA, EsA, Es2A, dpk, bits64, b3, bufB, 1);

    // readout
    gsum_kernel<<<BATCH, 256>>>(bufB, gsm);
    z2_kernel<<<BATCH, 64>>>(gsm, wg, bg, wv, z2p);
    final_kernel<<<M / 64, 256>>>(bufB, wn, bn, wv, bv, z2p, out);
}

// round 9
// speedup vs baseline: 1.8293x; 1.1057x over previous
#include <cuda_runtime.h>
#include <cuda_bf16.h>
#include <cstdint>

#define BATCH 8
#define NT    1024
typedef unsigned long long ull;
typedef unsigned int u32;

// ---------------- scratch (__device__ globals; no allocation allowed) ------
__device__ __align__(16) float g_bufA[BATCH * NT * 256];
__device__ __align__(16) float g_bufB[BATCH * NT * 256];
// scores, laid out [h][b][node]
__device__ __align__(16) float  g_sj [4 * BATCH * NT];
__device__ __align__(16) float  g_Esj[4 * BATCH * NT];
__device__ __align__(16) float  g_Es2[4 * BATCH * NT];
__device__ __align__(16) float4 g_dpk[4 * BATCH * NT];
// pre-transposed bf16-split features [h][b][c=64][node=1024]
__device__ __align__(16) __nv_bfloat16 g_hThi[4 * BATCH * 64 * NT];
__device__ __align__(16) __nv_bfloat16 g_hTlo[4 * BATCH * 64 * NT];
__device__ __align__(16) u32   g_bits[BATCH * NT * (NT / 32)];
__device__ __align__(16) float g_gsum[BATCH * 64];
__device__ __align__(16) float g_z2[BATCH];

// ---------------- helpers --------------------------------------------------
__device__ __forceinline__ uint32_t smem_u32(const void* p) {
    uint32_t a;
    asm("{ .reg .u64 t; cvta.to.shared.u64 t, %1; cvt.u32.u64 %0, t; }" : "=r"(a) : "l"(p));
    return a;
}

__device__ __forceinline__ void ldsm4(u32* r, u32 addr) {
    asm volatile("ldmatrix.sync.aligned.m8n8.x4.shared.b16 {%0,%1,%2,%3}, [%4];"
                 : "=r"(r[0]), "=r"(r[1]), "=r"(r[2]), "=r"(r[3]) : "r"(addr));
}

__device__ __forceinline__ void mma16816(float* c, const u32* a, u32 b0, u32 b1) {
    asm volatile(
        "mma.sync.aligned.m16n8k16.row.col.f32.bf16.bf16.f32 "
        "{%0,%1,%2,%3}, {%4,%5,%6,%7}, {%8,%9}, {%0,%1,%2,%3};"
        : "+f"(c[0]), "+f"(c[1]), "+f"(c[2]), "+f"(c[3])
        : "r"(a[0]), "r"(a[1]), "r"(a[2]), "r"(a[3]), "r"(b0), "r"(b1));
}

__device__ __forceinline__ float edgef(float s, float Es, float Es2, float4 dp, u32 bit) {
    float e = (s + dp.x > 0.f) ? Es * dp.y : Es2 * dp.z;
    return bit ? e : 0.f;
}

// pack two fp32 into bf16x2 (lower = ex, upper = ey) in one cvt
__device__ __forceinline__ u32 packbf2(float ex, float ey) {
    u32 r;
    asm("cvt.rn.bf16x2.f32 %0, %1, %2;" : "=r"(r) : "f"(ey), "f"(ex));
    return r;
}

// sum of the two bf16 values in a packed word, as fp32 (exact widening)
__device__ __forceinline__ float sum2bf(u32 p) {
    float a = __uint_as_float(p << 16);
    float b = __uint_as_float(p & 0xffff0000u);
    return a + b;
}

// hi/lo bf16 split of a pair, packed
__device__ __forceinline__ void split2(float x0, float x1, u32& hi, u32& lo) {
    hi = packbf2(x0, x1);
    float r0 = x0 - __uint_as_float(hi << 16);
    float r1 = x1 - __uint_as_float(hi & 0xffff0000u);
    lo = packbf2(r0, r1);
}

__device__ __forceinline__ unsigned short bf16of(float x) {
    u32 r = packbf2(x, 0.f);
    return (unsigned short)(r & 0xffffu);
}
__device__ __forceinline__ float bf16res(float x, unsigned short h) {
    return x - __uint_as_float((u32)h << 16);
}

__device__ __forceinline__ u32 swzf(u32 off) { return off ^ ((off >> 3) & 0x70); }

// ---------------- adj bit packing (with self loops) ------------------------
__global__ void pack_adj_kernel(const int* __restrict__ adj, u32* __restrict__ bits) {
    int row = blockIdx.x;                 // b*NT + i
    int lane = threadIdx.x;               // 32 threads
    int i = row & (NT - 1);
    const int* arow = adj + (size_t)row * NT;
    for (int w = 0; w < 32; w++) {
        int j = w * 32 + lane;
        int v = arow[j];
        unsigned m = __ballot_sync(0xffffffffu, (v > 0) || (j == i));
        if (lane == 0) bits[row * 32 + w] = m;
    }
}

// ---------------- fused HMMA feature GEMM + scores + split-transpose -------
// grid (M/128, H). Computes Y = X @ W[h*64..+63]^T on mma.sync (hi/lo split,
// 3 passes), then in the epilogue:
//   - per-node attention scores s,d (4-lane shfl reduce) + exp factors
//   - bf16 hi/lo split written transposed [h][b][c][node] via smem bounce
// Never writes the f32 feature tensor.
#define TPAD 136   // padded node count per c-row in bounce buffer (2B elems)
__global__ __launch_bounds__(256) void gemm_fused(
    const float* __restrict__ X, const float* __restrict__ W,
    const float* __restrict__ a_src, const float* __restrict__ a_dst,
    float* __restrict__ sj, float* __restrict__ Esj, float* __restrict__ Es2j,
    float4* __restrict__ dpk,
    __nv_bfloat16* __restrict__ hhi, __nv_bfloat16* __restrict__ hlo,
    int K)
{
    __shared__ __align__(128) char smbuf[49152];
    __nv_bfloat16* sXh = (__nv_bfloat16*)(smbuf);
    __nv_bfloat16* sXl = (__nv_bfloat16*)(smbuf + 16384);
    __nv_bfloat16* sWh = (__nv_bfloat16*)(smbuf + 32768);
    __nv_bfloat16* sWl = (__nv_bfloat16*)(smbuf + 40960);

    const int tid = threadIdx.x;
    const int w = tid >> 5, l = tid & 31;
    const int h = blockIdx.y;
    const int m0 = blockIdx.x * 128, n0 = h * 64;

    const u32 uXh = smem_u32(sXh), uXl = smem_u32(sXl);
    const u32 uWh = smem_u32(sWh), uWl = smem_u32(sWl);

    float acc[8][4];
#pragma unroll
    for (int ng = 0; ng < 8; ng++)
#pragma unroll
        for (int r = 0; r < 4; r++) acc[ng][r] = 0.f;

    // A-fragment ldmatrix row address (canonical x4 mapping)
    const int arow = w * 16 + (l & 7) + ((l >> 3) & 1) * 8;
    const int akh  = (l >> 4);
    // B-fragment address pieces
    const int sub = l >> 3;
    const int brow = (l & 7) + ((sub >> 1) << 3);

    for (int k0 = 0; k0 < K; k0 += 64) {
        __syncthreads();
        // ---- stage X tile (128x64) with inline bf16 split ----
#pragma unroll
        for (int i = 0; i < 4; i++) {
            int c = tid + i * 256;
            int row = c >> 3, kg = c & 7;
            const float* p = X + (size_t)(m0 + row) * K + k0 + kg * 8;
            float4 v0 = *(const float4*)p;
            float4 v1 = *(const float4*)(p + 4);
            u32 h0, h1, h2, h3, l0, l1, l2, l3;
            split2(v0.x, v0.y, h0, l0); split2(v0.z, v0.w, h1, l1);
            split2(v1.x, v1.y, h2, l2); split2(v1.z, v1.w, h3, l3);
            u32 off = swzf((u32)(row * 128 + kg * 16));
            *(uint4*)((char*)sXh + off) = make_uint4(h0, h1, h2, h3);
            *(uint4*)((char*)sXl + off) = make_uint4(l0, l1, l2, l3);
        }
        // ---- stage W tile (64x64) with inline bf16 split ----
#pragma unroll
        for (int i = 0; i < 2; i++) {
            int c = tid + i * 256;
            int row = c >> 3, kg = c & 7;
            const float* p = W + (size_t)(n0 + row) * K + k0 + kg * 8;
            float4 v0 = *(const float4*)p;
            float4 v1 = *(const float4*)(p + 4);
            u32 h0, h1, h2, h3, l0, l1, l2, l3;
            split2(v0.x, v0.y, h0, l0); split2(v0.z, v0.w, h1, l1);
            split2(v1.x, v1.y, h2, l2); split2(v1.z, v1.w, h3, l3);
            u32 off = swzf((u32)(row * 128 + kg * 16));
            *(uint4*)((char*)sWh + off) = make_uint4(h0, h1, h2, h3);
            *(uint4*)((char*)sWl + off) = make_uint4(l0, l1, l2, l3);
        }
        __syncthreads();

        // ---- compute: 4 k16 steps ----
#pragma unroll
        for (int q = 0; q < 4; q++) {
            u32 ah[4], al[4];
            u32 aoff = swzf((u32)(arow * 128 + q * 32 + akh * 16));
            ldsm4(ah, uXh + aoff);
            ldsm4(al, uXl + aoff);
            const int bchunk = 2 * q + (sub & 1);
            u32 bh[16], bl[16];
#pragma unroll
            for (int g = 0; g < 4; g++) {
                u32 off = swzf((u32)((g * 16 + brow) * 128 + bchunk * 16));
                ldsm4(bh + g * 4, uWh + off);
                ldsm4(bl + g * 4, uWl + off);
            }
#pragma unroll
            for (int g = 0; g < 4; g++) {
#pragma unroll
                for (int m = 0; m < 2; m++) {
                    int ng = g * 2 + m;
                    u32 b0 = bh[g * 4 + 2 * m], b1 = bh[g * 4 + 2 * m + 1];
                    u32 c0 = bl[g * 4 + 2 * m], c1 = bl[g * 4 + 2 * m + 1];
                    mma16816(acc[ng], ah, b0, b1);
                    mma16816(acc[ng], ah, c0, c1);
                    mma16816(acc[ng], al, b0, b1);
                }
            }
        }
    }

    const int r0 = w * 16 + (l >> 2);
    const int r1 = r0 + 8;

    // ---- epilogue 1: attention scores (4-lane reduce) ----
    {
        float s0 = 0.f, d0 = 0.f, s1 = 0.f, d1 = 0.f;
#pragma unroll
        for (int ng = 0; ng < 8; ng++) {
            int col = ng * 8 + 2 * (l & 3);
            float2 av = *(const float2*)(a_src + n0 + col);
            float2 dv = *(const float2*)(a_dst + n0 + col);
            s0 += acc[ng][0] * av.x + acc[ng][1] * av.y;
            d0 += acc[ng][0] * dv.x + acc[ng][1] * dv.y;
            s1 += acc[ng][2] * av.x + acc[ng][3] * av.y;
            d1 += acc[ng][2] * dv.x + acc[ng][3] * dv.y;
        }
        s0 += __shfl_xor_sync(0xffffffffu, s0, 1);
        s0 += __shfl_xor_sync(0xffffffffu, s0, 2);
        d0 += __shfl_xor_sync(0xffffffffu, d0, 1);
        d0 += __shfl_xor_sync(0xffffffffu, d0, 2);
        s1 += __shfl_xor_sync(0xffffffffu, s1, 1);
        s1 += __shfl_xor_sync(0xffffffffu, s1, 2);
        d1 += __shfl_xor_sync(0xffffffffu, d1, 1);
        d1 += __shfl_xor_sync(0xffffffffu, d1, 2);
        if ((l & 3) == 0) {
            int idx0 = h * (BATCH * NT) + m0 + r0;
            int idx1 = h * (BATCH * NT) + m0 + r1;
            sj[idx0]   = s0;
            Esj[idx0]  = __expf(s0);
            Es2j[idx0] = __expf(0.2f * s0);
            dpk[idx0]  = make_float4(d0, __expf(d0), __expf(0.2f * d0), 0.f);
            sj[idx1]   = s1;
            Esj[idx1]  = __expf(s1);
            Es2j[idx1] = __expf(0.2f * s1);
            dpk[idx1]  = make_float4(d1, __expf(d1), __expf(0.2f * d1), 0.f);
        }
    }

    // ---- epilogue 2: bf16 hi/lo split + transpose via smem bounce ----
    __syncthreads();   // done with operand smem
    unsigned short* Th = (unsigned short*)(smbuf);            // [64][TPAD]
    unsigned short* Tl = (unsigned short*)(smbuf + 64 * TPAD * 2);
#pragma unroll
    for (int ng = 0; ng < 8; ng++) {
        int col = ng * 8 + 2 * (l & 3);
#pragma unroll
        for (int v = 0; v < 4; v++) {
            int cc = col + (v & 1);
            int node = (v < 2) ? r0 : r1;
            float x = acc[ng][v];
            unsigned short hb = bf16of(x);
            float res = bf16res(x, hb);
            Th[cc * TPAD + node] = hb;
            Tl[cc * TPAD + node] = bf16of(res);
        }
    }
    __syncthreads();

    const int b = m0 >> 10;
    const int node0 = m0 & (NT - 1);
    const size_t gbase = ((size_t)((h * BATCH + b) * 64)) * NT + node0;
    {
        int c = tid >> 2;
#pragma unroll
        for (int i = 0; i < 4; i++) {
            int nch = (tid & 3) + 4 * i;
            uint4 vh = *(const uint4*)(Th + c * TPAD + nch * 8);
            uint4 vl = *(const uint4*)(Tl + c * TPAD + nch * 8);
            *(uint4*)(hhi + gbase + (size_t)c * NT + nch * 8) = vh;
            *(uint4*)(hlo + gbase + (size_t)c * NT + nch * 8) = vl;
        }
    }
}

// ---------------- HMMA aggregation -----------------------------------------
// grid (NT/128, H, B), 256 threads = 8 warps; warp w owns rows w*16..w*16+15.
// D[i,c] = sum_j E[i,j]*h[j,c] via mma.sync bf16.
// E quantized to bf16 (one A pass); B split hi/lo (2 passes).
// Rowsum accumulated from the QUANTIZED bf16 weights so the correlated
// per-row rounding of E cancels exactly in the normalization.
__global__ __launch_bounds__(256) void agg_mma_kernel(
    const __nv_bfloat16* __restrict__ hThi, const __nv_bfloat16* __restrict__ hTlo,
    const float* __restrict__ sjA, const float* __restrict__ EsA,
    const float* __restrict__ Es2A, const float4* __restrict__ dpk,
    const ull* __restrict__ bits64,
    const float* __restrict__ bias, float* __restrict__ xout, int H)
{
    __shared__ __align__(16) __nv_bfloat16 sh_h[2][2][64 * 64]; // [buf][hi/lo]
    __shared__ float sh_sc[2][3][64];                            // [buf][s/Es/Es2]

    const int tid = threadIdx.x;
    const int w = tid >> 5, l = tid & 31;
    const int b = blockIdx.z, h = blockIdx.y;
    const int i0 = blockIdx.x * 128;
    const int hb = h * BATCH + b;
    const int fs = H * 64;

    // row pair this thread accumulates (within 128-row strip)
    const int r0 = w * 16 + (l >> 2);
    const int r1 = r0 + 8;
    const float4 dp0 = dpk[hb * NT + i0 + r0];
    const float4 dp1 = dpk[hb * NT + i0 + r1];
    const ull* mrow0 = bits64 + (size_t)(b * NT + i0 + r0) * 16;
    const ull* mrow1 = bits64 + (size_t)(b * NT + i0 + r1) * 16;

    const float* sjp = sjA + hb * NT;
    const float* Esp = EsA + hb * NT;
    const float* Fsp = Es2A + hb * NT;
    const __nv_bfloat16* hhp = hThi + (size_t)hb * 64 * NT;
    const __nv_bfloat16* hlp = hTlo + (size_t)hb * 64 * NT;

    // h-tile staging mapping: thread handles chunks tid and tid+256 (16B each)
    const int c0 = tid >> 3, jc = tid & 7;
    const u32 st0 = swzf((u32)(c0 * 128 + jc * 16));
    const u32 st1 = swzf((u32)((c0 + 32) * 128 + jc * 16));
    // score staging
    const float* scsrc = (tid < 64) ? sjp : (tid < 128 ? Esp : Fsp);
    const int scidx = tid & 63;

    float acc[8][4];
#pragma unroll
    for (int ng = 0; ng < 8; ng++)
#pragma unroll
        for (int r = 0; r < 4; r++) acc[ng][r] = 0.f;
    float rs0 = 0.f, rs1 = 0.f;

    uint4 pvh0, pvh1, pvl0, pvl1;
    float psc = 0.f;

    auto ldg_tile = [&](int t) {
        int j0 = t * 64;
        pvh0 = *(const uint4*)(hhp + (size_t)c0 * NT + j0 + jc * 8);
        pvh1 = *(const uint4*)(hhp + (size_t)(c0 + 32) * NT + j0 + jc * 8);
        pvl0 = *(const uint4*)(hlp + (size_t)c0 * NT + j0 + jc * 8);
        pvl1 = *(const uint4*)(hlp + (size_t)(c0 + 32) * NT + j0 + jc * 8);
        if (tid < 192) psc = scsrc[j0 + scidx];
    };

    ldg_tile(0);

    const u32 su_hi[2] = { smem_u32(sh_h[0][0]), smem_u32(sh_h[1][0]) };
    const u32 su_lo[2] = { smem_u32(sh_h[0][1]), smem_u32(sh_h[1][1]) };

    for (int t = 0; t < 16; t++) {
        int buf = t & 1;
        // stage
        *(uint4*)((char*)sh_h[buf][0] + st0) = pvh0;
        *(uint4*)((char*)sh_h[buf][0] + st1) = pvh1;
        *(uint4*)((char*)sh_h[buf][1] + st0) = pvl0;
        *(uint4*)((char*)sh_h[buf][1] + st1) = pvl1;
        if (tid < 192) sh_sc[buf][tid >> 6][scidx] = psc;
        __syncthreads();
        if (t < 15) ldg_tile(t + 1);

        const float* scS = sh_sc[buf][0];
        const float* scE = sh_sc[buf][1];
        const float* scF = sh_sc[buf][2];
        const ull m0 = mrow0[t];
        const ull m1 = mrow1[t];

#pragma unroll
        for (int q = 0; q < 4; q++) {
            const int jA = q * 16 + 2 * (l & 3);
            float s0 = scS[jA], s1 = scS[jA + 1], s2 = scS[jA + 8], s3 = scS[jA + 9];
            float E0 = scE[jA], E1 = scE[jA + 1], E2 = scE[jA + 8], E3 = scE[jA + 9];
            float F0 = scF[jA], F1 = scF[jA + 1], F2 = scF[jA + 8], F3 = scF[jA + 9];

            u32 ahi[4];
            // row r0
            {
                float eA = edgef(s0, E0, F0, dp0, (u32)(m0 >> jA) & 1u);
                float eB = edgef(s1, E1, F1, dp0, (u32)(m0 >> (jA + 1)) & 1u);
                float eC = edgef(s2, E2, F2, dp0, (u32)(m0 >> (jA + 8)) & 1u);
                float eD = edgef(s3, E3, F3, dp0, (u32)(m0 >> (jA + 9)) & 1u);
                ahi[0] = packbf2(eA, eB);
                ahi[2] = packbf2(eC, eD);
                rs0 += sum2bf(ahi[0]) + sum2bf(ahi[2]);
            }
            // row r1
            {
                float eA = edgef(s0, E0, F0, dp1, (u32)(m1 >> jA) & 1u);
                float eB = edgef(s1, E1, F1, dp1, (u32)(m1 >> (jA + 1)) & 1u);
                float eC = edgef(s2, E2, F2, dp1, (u32)(m1 >> (jA + 8)) & 1u);
                float eD = edgef(s3, E3, F3, dp1, (u32)(m1 >> (jA + 9)) & 1u);
                ahi[1] = packbf2(eA, eB);
                ahi[3] = packbf2(eC, eD);
                rs1 += sum2bf(ahi[1]) + sum2bf(ahi[3]);
            }

            // B fragments via ldmatrix (layout [n][k], k-contiguous, SW swizzled)
            u32 bh[16], bl[16];
            const int sub = l >> 3;
            const int brow = (l & 7) + ((sub >> 1) << 3);
            const int bchunk = 2 * q + (sub & 1);
#pragma unroll
            for (int g = 0; g < 4; g++) {
                u32 off = swzf((u32)((g * 16 + brow) * 128 + bchunk * 16));
                ldsm4(bh + g * 4, su_hi[buf] + off);
                ldsm4(bl + g * 4, su_lo[buf] + off);
            }
#pragma unroll
            for (int g = 0; g < 4; g++) {
#pragma unroll
                for (int m = 0; m < 2; m++) {
                    int ng = g * 2 + m;
                    u32 h0 = bh[g * 4 + 2 * m], h1 = bh[g * 4 + 2 * m + 1];
                    u32 l0 = bl[g * 4 + 2 * m], l1 = bl[g * 4 + 2 * m + 1];
                    mma16816(acc[ng], ahi, h0, h1);
                    mma16816(acc[ng], ahi, l0, l1);
                }
            }
        }
        __syncthreads();
    }

    // rowsum reduce across the 4 lanes that share a row
    rs0 += __shfl_xor_sync(0xffffffffu, rs0, 1);
    rs0 += __shfl_xor_sync(0xffffffffu, rs0, 2);
    rs1 += __shfl_xor_sync(0xffffffffu, rs1, 1);
    rs1 += __shfl_xor_sync(0xffffffffu, rs1, 2);
    float rinv0 = 1.0f / rs0;
    float rinv1 = 1.0f / rs1;

    float* orow0 = xout + (size_t)(b * NT + i0 + r0) * fs + h * 64;
    float* orow1 = xout + (size_t)(b * NT + i0 + r1) * fs + h * 64;
#pragma unroll
    for (int ng = 0; ng < 8; ng++) {
        int col = ng * 8 + 2 * (l & 3);
        float2 bb = *(const float2*)(bias + h * 64 + col);
        float2 o0, o1;
        o0.x = fmaxf(acc[ng][0] * rinv0 + bb.x, 0.f);
        o0.y = fmaxf(acc[ng][1] * rinv0 + bb.y, 0.f);
        o1.x = fmaxf(acc[ng][2] * rinv1 + bb.x, 0.f);
        o1.y = fmaxf(acc[ng][3] * rinv1 + bb.y, 0.f);
        *(float2*)(orow0 + col) = o0;
        *(float2*)(orow1 + col) = o1;
    }
}

// ---------------- readout --------------------------------------------------
__global__ void gsum_kernel(const float* __restrict__ x, float* __restrict__ g) {
    int b = blockIdx.x;
    int tid = threadIdx.x;
    int c = tid & 63, nq = tid >> 6;
    float acc = 0.f;
    for (int n = nq; n < NT; n += 4) acc += x[((size_t)b * NT + n) * 64 + c];
    __shared__ float sm[256];
    sm[tid] = acc;
    __syncthreads();
    if (tid < 64) g[b * 64 + tid] = sm[tid] + sm[64 + tid] + sm[128 + tid] + sm[192 + tid];
}

__global__ void z2_kernel(const float* __restrict__ g, const float* __restrict__ wg,
                          const float* __restrict__ bg, const float* __restrict__ wv,
                          float* __restrict__ z2) {
    int b = blockIdx.x;
    int c = threadIdx.x;
    float acc = bg[c];
    for (int k = 0; k < 64; k++) acc += g[b * 64 + k] * wg[c * 64 + k];
    float y = fmaxf(acc, 0.f) * wv[64 + c];
    __shared__ float sm[64];
    sm[c] = y;
    __syncthreads();
    if (c == 0) {
        float t = 0.f;
        for (int k = 0; k < 64; k++) t += sm[k];
        z2[b] = t;
    }
}

__global__ __launch_bounds__(256) void final_kernel(
    const float* __restrict__ x,
    const float* __restrict__ wn, const float* __restrict__ bn,
    const float* __restrict__ wv, const float* __restrict__ bv,
    const float* __restrict__ z2, float* __restrict__ out)
{
    __shared__ float wns[64][65];
    __shared__ float bns[64], wvs[64];
    int tid = threadIdx.x;
#pragma unroll
    for (int l = 0; l < 16; l++) {
        int f = tid + l * 256;
        wns[f >> 6][f & 63] = wn[f];
    }
    if (tid < 64) { bns[tid] = bn[tid]; wvs[tid] = wv[tid]; }
    __syncthreads();

    int row = blockIdx.x * 64 + (tid >> 2);
    int q = tid & 3;
    float xr[64];
#pragma unroll
    for (int k = 0; k < 64; k++) xr[k] = x[(size_t)row * 64 + k];
    float y = 0.f;
    for (int c16 = 0; c16 < 16; c16++) {
        int c = q * 16 + c16;
        float acc = bns[c];
#pragma unroll
        for (int k = 0; k < 64; k++) acc += xr[k] * wns[c][k];
        y += fmaxf(acc, 0.f) * wvs[c];
    }
    y += __shfl_xor_sync(0xffffffffu, y, 1);
    y += __shfl_xor_sync(0xffffffffu, y, 2);
    if (q == 0) out[row] = y + z2[row >> 10] + bv[0];
}

// ---------------- launch ----------------------------------------------------
extern "C" void kernel_launch(void* const* d_in, const int* in_sizes, int n_in,
                              void* d_out, int out_size)
{
    const float* xin = (const float*)d_in[0];
    const int*   adj = (const int*)d_in[1];
    const float* w1  = (const float*)d_in[2];
    const float* as1 = (const float*)d_in[3];
    const float* ad1 = (const float*)d_in[4];
    const float* b1  = (const float*)d_in[5];
    const float* w2  = (const float*)d_in[6];
    const float* as2 = (const float*)d_in[7];
    const float* ad2 = (const float*)d_in[8];
    const float* b2  = (const float*)d_in[9];
    const float* w3  = (const float*)d_in[10];
    const float* as3 = (const float*)d_in[11];
    const float* ad3 = (const float*)d_in[12];
    const float* b3  = (const float*)d_in[13];
    const float* wn  = (const float*)d_in[14];
    const float* bn  = (const float*)d_in[15];
    const float* wg  = (const float*)d_in[16];
    const float* bg  = (const float*)d_in[17];
    const float* wv  = (const float*)d_in[18];
    const float* bv  = (const float*)d_in[19];
    float* out = (float*)d_out;

    float *bufA, *bufB, *sA, *EsA, *Es2A, *gsm, *z2p;
    float4* dpk;
    __nv_bfloat16 *hhi, *hlo;
    u32* bits;
    cudaGetSymbolAddress((void**)&bufA, g_bufA);
    cudaGetSymbolAddress((void**)&bufB, g_bufB);
    cudaGetSymbolAddress((void**)&sA,   g_sj);
    cudaGetSymbolAddress((void**)&EsA,  g_Esj);
    cudaGetSymbolAddress((void**)&Es2A, g_Es2);
    cudaGetSymbolAddress((void**)&dpk,  g_dpk);
    cudaGetSymbolAddress((void**)&hhi,  g_hThi);
    cudaGetSymbolAddress((void**)&hlo,  g_hTlo);
    cudaGetSymbolAddress((void**)&bits, g_bits);
    cudaGetSymbolAddress((void**)&gsm,  g_gsum);
    cudaGetSymbolAddress((void**)&z2p,  g_z2);

    const int M = BATCH * NT;
    const ull* bits64 = (const ull*)bits;

    pack_adj_kernel<<<M, 32>>>(adj, bits);

    // layer 1: 64 -> 4x64 (gemm + scores + split-transpose fused)
    gemm_fused<<<dim3(M / 128, 4), 256>>>(xin, w1, as1, ad1,
                                          sA, EsA, Es2A, dpk, hhi, hlo, 64);
    agg_mma_kernel<<<dim3(NT / 128, 4, BATCH), 256>>>(
        hhi, hlo, sA, EsA, Es2A, dpk, bits64, b1, bufB, 4);

    // layer 2: 4x64 -> 4x64
    gemm_fused<<<dim3(M / 128, 4), 256>>>(bufB, w2, as2, ad2,
                                          sA, EsA, Es2A, dpk, hhi, hlo, 256);
    agg_mma_kernel<<<dim3(NT / 128, 4, BATCH), 256>>>(
        hhi, hlo, sA, EsA, Es2A, dpk, bits64, b2, bufA, 4);

    // layer 3: 4x64 -> 64 (H=1)
    gemm_fused<<<dim3(M / 128, 1), 256>>>(bufA, w3, as3, ad3,
                                          sA, EsA, Es2A, dpk, hhi, hlo, 256);
    agg_mma_kernel<<<dim3(NT / 128, 1, BATCH), 256>>>(
        hhi, hlo, sA, EsA, Es2A, dpk, bits64, b3, bufB, 1);

    // readout
    gsum_kernel<<<BATCH, 256>>>(bufB, gsm);
    z2_kernel<<<BATCH, 64>>>(gsm, wg, bg, wv, z2p);
    final_kernel<<<M / 64, 256>>>(bufB, wn, bn, wv, bv, z2p, out);
}

// round 10
// speedup vs baseline: 1.8526x; 1.0127x over previous
#include <cuda_runtime.h>
#include <cuda_bf16.h>
#include <cstdint>

#define BATCH 8
#define NT    1024
typedef unsigned long long ull;
typedef unsigned int u32;

// ---------------- scratch (__device__ globals; no allocation allowed) ------
__device__ __align__(16) float g_bufA[BATCH * NT * 256];
__device__ __align__(16) float g_bufB[BATCH * NT * 256];
// scores, laid out [h][b][node]
__device__ __align__(16) float  g_sj [4 * BATCH * NT];
__device__ __align__(16) float  g_Esj[4 * BATCH * NT];
__device__ __align__(16) float  g_Es2[4 * BATCH * NT];
__device__ __align__(16) float4 g_dpk[4 * BATCH * NT];
// pre-transposed bf16-split features [h][b][c=64][node=1024]
__device__ __align__(16) __nv_bfloat16 g_hThi[4 * BATCH * 64 * NT];
__device__ __align__(16) __nv_bfloat16 g_hTlo[4 * BATCH * 64 * NT];
__device__ __align__(16) u32   g_bits[BATCH * NT * (NT / 32)];
__device__ __align__(16) float g_gsum[BATCH * 64];
__device__ __align__(16) float g_z2[BATCH];

// ---------------- helpers --------------------------------------------------
__device__ __forceinline__ uint32_t smem_u32(const void* p) {
    uint32_t a;
    asm("{ .reg .u64 t; cvta.to.shared.u64 t, %1; cvt.u32.u64 %0, t; }" : "=r"(a) : "l"(p));
    return a;
}

__device__ __forceinline__ void ldsm4(u32* r, u32 addr) {
    asm volatile("ldmatrix.sync.aligned.m8n8.x4.shared.b16 {%0,%1,%2,%3}, [%4];"
                 : "=r"(r[0]), "=r"(r[1]), "=r"(r[2]), "=r"(r[3]) : "r"(addr));
}

__device__ __forceinline__ void mma16816(float* c, const u32* a, u32 b0, u32 b1) {
    asm volatile(
        "mma.sync.aligned.m16n8k16.row.col.f32.bf16.bf16.f32 "
        "{%0,%1,%2,%3}, {%4,%5,%6,%7}, {%8,%9}, {%0,%1,%2,%3};"
        : "+f"(c[0]), "+f"(c[1]), "+f"(c[2]), "+f"(c[3])
        : "r"(a[0]), "r"(a[1]), "r"(a[2]), "r"(a[3]), "r"(b0), "r"(b1));
}

// edge weight with row scale 1/Ed_i factored out (cancels in softmax):
// e' = (s_j + d_i > 0) ? Es_j : rho_i * Es2_j   (rho_i = exp(-0.8 d_i))
__device__ __forceinline__ float edgef(float s, float Es, float Es2,
                                       float d, float rho, u32 bit) {
    float e = (s + d > 0.f) ? Es : rho * Es2;
    return bit ? e : 0.f;
}

// pack two fp32 into bf16x2 (lower = ex, upper = ey) in one cvt
__device__ __forceinline__ u32 packbf2(float ex, float ey) {
    u32 r;
    asm("cvt.rn.bf16x2.f32 %0, %1, %2;" : "=r"(r) : "f"(ey), "f"(ex));
    return r;
}

// hi/lo bf16 split of a pair, packed
__device__ __forceinline__ void split2(float x0, float x1, u32& hi, u32& lo) {
    hi = packbf2(x0, x1);
    float r0 = x0 - __uint_as_float(hi << 16);
    float r1 = x1 - __uint_as_float(hi & 0xffff0000u);
    lo = packbf2(r0, r1);
}

__device__ __forceinline__ unsigned short bf16of(float x) {
    u32 r = packbf2(x, 0.f);
    return (unsigned short)(r & 0xffffu);
}
__device__ __forceinline__ float bf16res(float x, unsigned short h) {
    return x - __uint_as_float((u32)h << 16);
}

__device__ __forceinline__ u32 swzf(u32 off) { return off ^ ((off >> 3) & 0x70); }

#define ONES2 0x3F803F80u   // two bf16 1.0

// ---------------- adj bit packing (with self loops) ------------------------
__global__ void pack_adj_kernel(const int* __restrict__ adj, u32* __restrict__ bits) {
    int row = blockIdx.x;                 // b*NT + i
    int lane = threadIdx.x;               // 32 threads
    int i = row & (NT - 1);
    const int* arow = adj + (size_t)row * NT;
    for (int w = 0; w < 32; w++) {
        int j = w * 32 + lane;
        int v = arow[j];
        unsigned m = __ballot_sync(0xffffffffu, (v > 0) || (j == i));
        if (lane == 0) bits[row * 32 + w] = m;
    }
}

// ---------------- fused HMMA feature GEMM + scores + split-transpose -------
#define TPAD 136
__global__ __launch_bounds__(256) void gemm_fused(
    const float* __restrict__ X, const float* __restrict__ W,
    const float* __restrict__ a_src, const float* __restrict__ a_dst,
    float* __restrict__ sj, float* __restrict__ Esj, float* __restrict__ Es2j,
    float4* __restrict__ dpk,
    __nv_bfloat16* __restrict__ hhi, __nv_bfloat16* __restrict__ hlo,
    int K)
{
    __shared__ __align__(128) char smbuf[49152];
    __nv_bfloat16* sXh = (__nv_bfloat16*)(smbuf);
    __nv_bfloat16* sXl = (__nv_bfloat16*)(smbuf + 16384);
    __nv_bfloat16* sWh = (__nv_bfloat16*)(smbuf + 32768);
    __nv_bfloat16* sWl = (__nv_bfloat16*)(smbuf + 40960);

    const int tid = threadIdx.x;
    const int w = tid >> 5, l = tid & 31;
    const int h = blockIdx.y;
    const int m0 = blockIdx.x * 128, n0 = h * 64;

    const u32 uXh = smem_u32(sXh), uXl = smem_u32(sXl);
    const u32 uWh = smem_u32(sWh), uWl = smem_u32(sWl);

    float acc[8][4];
#pragma unroll
    for (int ng = 0; ng < 8; ng++)
#pragma unroll
        for (int r = 0; r < 4; r++) acc[ng][r] = 0.f;

    const int arow = w * 16 + (l & 7) + ((l >> 3) & 1) * 8;
    const int akh  = (l >> 4);
    const int sub = l >> 3;
    const int brow = (l & 7) + ((sub >> 1) << 3);

    for (int k0 = 0; k0 < K; k0 += 64) {
        __syncthreads();
#pragma unroll
        for (int i = 0; i < 4; i++) {
            int c = tid + i * 256;
            int row = c >> 3, kg = c & 7;
            const float* p = X + (size_t)(m0 + row) * K + k0 + kg * 8;
            float4 v0 = *(const float4*)p;
            float4 v1 = *(const float4*)(p + 4);
            u32 h0, h1, h2, h3, l0, l1, l2, l3;
            split2(v0.x, v0.y, h0, l0); split2(v0.z, v0.w, h1, l1);
            split2(v1.x, v1.y, h2, l2); split2(v1.z, v1.w, h3, l3);
            u32 off = swzf((u32)(row * 128 + kg * 16));
            *(uint4*)((char*)sXh + off) = make_uint4(h0, h1, h2, h3);
            *(uint4*)((char*)sXl + off) = make_uint4(l0, l1, l2, l3);
        }
#pragma unroll
        for (int i = 0; i < 2; i++) {
            int c = tid + i * 256;
            int row = c >> 3, kg = c & 7;
            const float* p = W + (size_t)(n0 + row) * K + k0 + kg * 8;
            float4 v0 = *(const float4*)p;
            float4 v1 = *(const float4*)(p + 4);
            u32 h0, h1, h2, h3, l0, l1, l2, l3;
            split2(v0.x, v0.y, h0, l0); split2(v0.z, v0.w, h1, l1);
            split2(v1.x, v1.y, h2, l2); split2(v1.z, v1.w, h3, l3);
            u32 off = swzf((u32)(row * 128 + kg * 16));
            *(uint4*)((char*)sWh + off) = make_uint4(h0, h1, h2, h3);
            *(uint4*)((char*)sWl + off) = make_uint4(l0, l1, l2, l3);
        }
        __syncthreads();

#pragma unroll
        for (int q = 0; q < 4; q++) {
            u32 ah[4], al[4];
            u32 aoff = swzf((u32)(arow * 128 + q * 32 + akh * 16));
            ldsm4(ah, uXh + aoff);
            ldsm4(al, uXl + aoff);
            const int bchunk = 2 * q + (sub & 1);
            u32 bh[16], bl[16];
#pragma unroll
            for (int g = 0; g < 4; g++) {
                u32 off = swzf((u32)((g * 16 + brow) * 128 + bchunk * 16));
                ldsm4(bh + g * 4, uWh + off);
                ldsm4(bl + g * 4, uWl + off);
            }
#pragma unroll
            for (int g = 0; g < 4; g++) {
#pragma unroll
                for (int m = 0; m < 2; m++) {
                    int ng = g * 2 + m;
                    u32 b0 = bh[g * 4 + 2 * m], b1 = bh[g * 4 + 2 * m + 1];
                    u32 c0 = bl[g * 4 + 2 * m], c1 = bl[g * 4 + 2 * m + 1];
                    mma16816(acc[ng], ah, b0, b1);
                    mma16816(acc[ng], ah, c0, c1);
                    mma16816(acc[ng], al, b0, b1);
                }
            }
        }
    }

    const int r0 = w * 16 + (l >> 2);
    const int r1 = r0 + 8;

    // ---- epilogue 1: attention scores (4-lane reduce) ----
    {
        float s0 = 0.f, d0 = 0.f, s1 = 0.f, d1 = 0.f;
#pragma unroll
        for (int ng = 0; ng < 8; ng++) {
            int col = ng * 8 + 2 * (l & 3);
            float2 av = *(const float2*)(a_src + n0 + col);
            float2 dv = *(const float2*)(a_dst + n0 + col);
            s0 += acc[ng][0] * av.x + acc[ng][1] * av.y;
            d0 += acc[ng][0] * dv.x + acc[ng][1] * dv.y;
            s1 += acc[ng][2] * av.x + acc[ng][3] * av.y;
            d1 += acc[ng][2] * dv.x + acc[ng][3] * dv.y;
        }
        s0 += __shfl_xor_sync(0xffffffffu, s0, 1);
        s0 += __shfl_xor_sync(0xffffffffu, s0, 2);
        d0 += __shfl_xor_sync(0xffffffffu, d0, 1);
        d0 += __shfl_xor_sync(0xffffffffu, d0, 2);
        s1 += __shfl_xor_sync(0xffffffffu, s1, 1);
        s1 += __shfl_xor_sync(0xffffffffu, s1, 2);
        d1 += __shfl_xor_sync(0xffffffffu, d1, 1);
        d1 += __shfl_xor_sync(0xffffffffu, d1, 2);
        if ((l & 3) == 0) {
            int idx0 = h * (BATCH * NT) + m0 + r0;
            int idx1 = h * (BATCH * NT) + m0 + r1;
            sj[idx0]   = s0;
            Esj[idx0]  = __expf(s0);
            Es2j[idx0] = __expf(0.2f * s0);
            dpk[idx0]  = make_float4(d0, __expf(-0.8f * d0), 0.f, 0.f);
            sj[idx1]   = s1;
            Esj[idx1]  = __expf(s1);
            Es2j[idx1] = __expf(0.2f * s1);
            dpk[idx1]  = make_float4(d1, __expf(-0.8f * d1), 0.f, 0.f);
        }
    }

    // ---- epilogue 2: bf16 hi/lo split + transpose via smem bounce ----
    __syncthreads();
    unsigned short* Th = (unsigned short*)(smbuf);            // [64][TPAD]
    unsigned short* Tl = (unsigned short*)(smbuf + 64 * TPAD * 2);
#pragma unroll
    for (int ng = 0; ng < 8; ng++) {
        int col = ng * 8 + 2 * (l & 3);
#pragma unroll
        for (int v = 0; v < 4; v++) {
            int cc = col + (v & 1);
            int node = (v < 2) ? r0 : r1;
            float x = acc[ng][v];
            unsigned short hb = bf16of(x);
            float res = bf16res(x, hb);
            Th[cc * TPAD + node] = hb;
            Tl[cc * TPAD + node] = bf16of(res);
        }
    }
    __syncthreads();

    const int b = m0 >> 10;
    const int node0 = m0 & (NT - 1);
    const size_t gbase = ((size_t)((h * BATCH + b) * 64)) * NT + node0;
    {
        int c = tid >> 2;
#pragma unroll
        for (int i = 0; i < 4; i++) {
            int nch = (tid & 3) + 4 * i;
            uint4 vh = *(const uint4*)(Th + c * TPAD + nch * 8);
            uint4 vl = *(const uint4*)(Tl + c * TPAD + nch * 8);
            *(uint4*)(hhi + gbase + (size_t)c * NT + nch * 8) = vh;
            *(uint4*)(hlo + gbase + (size_t)c * NT + nch * 8) = vl;
        }
    }
}

// ---------------- HMMA aggregation -----------------------------------------
// grid (NT/128, H, B), 256 threads = 8 warps; warp w owns rows w*16..w*16+15.
// D[i,c] = sum_j E'[i,j]*h[j,c] via mma.sync bf16 (row scale 1/Ed_i factored
// out; cancels in softmax). E' quantized to bf16 (1 A pass), B split hi/lo.
// Rowsum = MMA of the same quantized A fragment against all-ones B, so the
// correlated quantization of E' cancels exactly and no shfl reduce is needed.
__global__ __launch_bounds__(256, 2) void agg_mma_kernel(
    const __nv_bfloat16* __restrict__ hThi, const __nv_bfloat16* __restrict__ hTlo,
    const float* __restrict__ sjA, const float* __restrict__ EsA,
    const float* __restrict__ Es2A, const float4* __restrict__ dpk,
    const ull* __restrict__ bits64,
    const float* __restrict__ bias, float* __restrict__ xout, int H)
{
    __shared__ __align__(16) __nv_bfloat16 sh_h[2][2][64 * 64]; // [buf][hi/lo]
    __shared__ float sh_sc[2][3][64];                            // [buf][s/Es/Es2]

    const int tid = threadIdx.x;
    const int w = tid >> 5, l = tid & 31;
    const int b = blockIdx.z, h = blockIdx.y;
    const int i0 = blockIdx.x * 128;
    const int hb = h * BATCH + b;
    const int fs = H * 64;

    const int r0 = w * 16 + (l >> 2);
    const int r1 = r0 + 8;
    const float4 dp0 = dpk[hb * NT + i0 + r0];
    const float4 dp1 = dpk[hb * NT + i0 + r1];
    const ull* mrow0 = bits64 + (size_t)(b * NT + i0 + r0) * 16;
    const ull* mrow1 = bits64 + (size_t)(b * NT + i0 + r1) * 16;

    const float* sjp = sjA + hb * NT;
    const float* Esp = EsA + hb * NT;
    const float* Fsp = Es2A + hb * NT;
    const __nv_bfloat16* hhp = hThi + (size_t)hb * 64 * NT;
    const __nv_bfloat16* hlp = hTlo + (size_t)hb * 64 * NT;

    const int c0 = tid >> 3, jc = tid & 7;
    const u32 st0 = swzf((u32)(c0 * 128 + jc * 16));
    const u32 st1 = swzf((u32)((c0 + 32) * 128 + jc * 16));
    const float* scsrc = (tid < 64) ? sjp : (tid < 128 ? Esp : Fsp);
    const int scidx = tid & 63;

    float acc[8][4];
#pragma unroll
    for (int ng = 0; ng < 8; ng++)
#pragma unroll
        for (int r = 0; r < 4; r++) acc[ng][r] = 0.f;
    float accrs[4] = {0.f, 0.f, 0.f, 0.f};   // rowsum accumulator (ones-B MMA)

    uint4 pvh0, pvh1, pvl0, pvl1;
    float psc = 0.f;

    auto ldg_tile = [&](int t) {
        int j0 = t * 64;
        pvh0 = *(const uint4*)(hhp + (size_t)c0 * NT + j0 + jc * 8);
        pvh1 = *(const uint4*)(hhp + (size_t)(c0 + 32) * NT + j0 + jc * 8);
        pvl0 = *(const uint4*)(hlp + (size_t)c0 * NT + j0 + jc * 8);
        pvl1 = *(const uint4*)(hlp + (size_t)(c0 + 32) * NT + j0 + jc * 8);
        if (tid < 192) psc = scsrc[j0 + scidx];
    };

    ldg_tile(0);

    const u32 su_hi[2] = { smem_u32(sh_h[0][0]), smem_u32(sh_h[1][0]) };
    const u32 su_lo[2] = { smem_u32(sh_h[0][1]), smem_u32(sh_h[1][1]) };

    for (int t = 0; t < 16; t++) {
        int buf = t & 1;
        *(uint4*)((char*)sh_h[buf][0] + st0) = pvh0;
        *(uint4*)((char*)sh_h[buf][0] + st1) = pvh1;
        *(uint4*)((char*)sh_h[buf][1] + st0) = pvl0;
        *(uint4*)((char*)sh_h[buf][1] + st1) = pvl1;
        if (tid < 192) sh_sc[buf][tid >> 6][scidx] = psc;
        __syncthreads();
        if (t < 15) ldg_tile(t + 1);

        const float* scS = sh_sc[buf][0];
        const float* scE = sh_sc[buf][1];
        const float* scF = sh_sc[buf][2];
        const ull m0 = mrow0[t];
        const ull m1 = mrow1[t];

#pragma unroll
        for (int q = 0; q < 4; q++) {
            const int jA = q * 16 + 2 * (l & 3);
            float s0 = scS[jA], s1 = scS[jA + 1], s2 = scS[jA + 8], s3 = scS[jA + 9];
            float E0 = scE[jA], E1 = scE[jA + 1], E2 = scE[jA + 8], E3 = scE[jA + 9];
            float F0 = scF[jA], F1 = scF[jA + 1], F2 = scF[jA + 8], F3 = scF[jA + 9];

            u32 ahi[4];
            // row r0
            {
                float eA = edgef(s0, E0, F0, dp0.x, dp0.y, (u32)(m0 >> jA) & 1u);
                float eB = edgef(s1, E1, F1, dp0.x, dp0.y, (u32)(m0 >> (jA + 1)) & 1u);
                float eC = edgef(s2, E2, F2, dp0.x, dp0.y, (u32)(m0 >> (jA + 8)) & 1u);
                float eD = edgef(s3, E3, F3, dp0.x, dp0.y, (u32)(m0 >> (jA + 9)) & 1u);
                ahi[0] = packbf2(eA, eB);
                ahi[2] = packbf2(eC, eD);
            }
            // row r1
            {
                float eA = edgef(s0, E0, F0, dp1.x, dp1.y, (u32)(m1 >> jA) & 1u);
                float eB = edgef(s1, E1, F1, dp1.x, dp1.y, (u32)(m1 >> (jA + 1)) & 1u);
                float eC = edgef(s2, E2, F2, dp1.x, dp1.y, (u32)(m1 >> (jA + 8)) & 1u);
                float eD = edgef(s3, E3, F3, dp1.x, dp1.y, (u32)(m1 >> (jA + 9)) & 1u);
                ahi[1] = packbf2(eA, eB);
                ahi[3] = packbf2(eC, eD);
            }

            // rowsum of the quantized weights via ones-B MMA
            mma16816(accrs, ahi, ONES2, ONES2);

            // B fragments via ldmatrix
            u32 bh[16], bl[16];
            const int sub = l >> 3;
            const int brow = (l & 7) + ((sub >> 1) << 3);
            const int bchunk = 2 * q + (sub & 1);
#pragma unroll
            for (int g = 0; g < 4; g++) {
                u32 off = swzf((u32)((g * 16 + brow) * 128 + bchunk * 16));
                ldsm4(bh + g * 4, su_hi[buf] + off);
                ldsm4(bl + g * 4, su_lo[buf] + off);
            }
#pragma unroll
            for (int g = 0; g < 4; g++) {
#pragma unroll
                for (int m = 0; m < 2; m++) {
                    int ng = g * 2 + m;
                    u32 h0 = bh[g * 4 + 2 * m], h1 = bh[g * 4 + 2 * m + 1];
                    u32 l0 = bl[g * 4 + 2 * m], l1 = bl[g * 4 + 2 * m + 1];
                    mma16816(acc[ng], ahi, h0, h1);
                    mma16816(acc[ng], ahi, l0, l1);
                }
            }
        }
        __syncthreads();
    }

    float rinv0 = 1.0f / accrs[0];
    float rinv1 = 1.0f / accrs[2];

    float* orow0 = xout + (size_t)(b * NT + i0 + r0) * fs + h * 64;
    float* orow1 = xout + (size_t)(b * NT + i0 + r1) * fs + h * 64;
#pragma unroll
    for (int ng = 0; ng < 8; ng++) {
        int col = ng * 8 + 2 * (l & 3);
        float2 bb = *(const float2*)(bias + h * 64 + col);
        float2 o0, o1;
        o0.x = fmaxf(acc[ng][0] * rinv0 + bb.x, 0.f);
        o0.y = fmaxf(acc[ng][1] * rinv0 + bb.y, 0.f);
        o1.x = fmaxf(acc[ng][2] * rinv1 + bb.x, 0.f);
        o1.y = fmaxf(acc[ng][3] * rinv1 + bb.y, 0.f);
        *(float2*)(orow0 + col) = o0;
        *(float2*)(orow1 + col) = o1;
    }
}

// ---------------- readout --------------------------------------------------
__global__ void gsum_kernel(const float* __restrict__ x, float* __restrict__ g) {
    int b = blockIdx.x;
    int tid = threadIdx.x;
    int c = tid & 63, nq = tid >> 6;
    float acc = 0.f;
    for (int n = nq; n < NT; n += 4) acc += x[((size_t)b * NT + n) * 64 + c];
    __shared__ float sm[256];
    sm[tid] = acc;
    __syncthreads();
    if (tid < 64) g[b * 64 + tid] = sm[tid] + sm[64 + tid] + sm[128 + tid] + sm[192 + tid];
}

__global__ void z2_kernel(const float* __restrict__ g, const float* __restrict__ wg,
                          const float* __restrict__ bg, const float* __restrict__ wv,
                          float* __restrict__ z2) {
    int b = blockIdx.x;
    int c = threadIdx.x;
    float acc = bg[c];
    for (int k = 0; k < 64; k++) acc += g[b * 64 + k] * wg[c * 64 + k];
    float y = fmaxf(acc, 0.f) * wv[64 + c];
    __shared__ float sm[64];
    sm[c] = y;
    __syncthreads();
    if (c == 0) {
        float t = 0.f;
        for (int k = 0; k < 64; k++) t += sm[k];
        z2[b] = t;
    }
}

__global__ __launch_bounds__(256) void final_kernel(
    const float* __restrict__ x,
    const float* __restrict__ wn, const float* __restrict__ bn,
    const float* __restrict__ wv, const float* __restrict__ bv,
    const float* __restrict__ z2, float* __restrict__ out)
{
    __shared__ float wns[64][65];
    __shared__ float bns[64], wvs[64];
    int tid = threadIdx.x;
#pragma unroll
    for (int l = 0; l < 16; l++) {
        int f = tid + l * 256;
        wns[f >> 6][f & 63] = wn[f];
    }
    if (tid < 64) { bns[tid] = bn[tid]; wvs[tid] = wv[tid]; }
    __syncthreads();

    int row = blockIdx.x * 64 + (tid >> 2);
    int q = tid & 3;
    float xr[64];
#pragma unroll
    for (int k = 0; k < 64; k++) xr[k] = x[(size_t)row * 64 + k];
    float y = 0.f;
    for (int c16 = 0; c16 < 16; c16++) {
        int c = q * 16 + c16;
        float acc = bns[c];
#pragma unroll
        for (int k = 0; k < 64; k++) acc += xr[k] * wns[c][k];
        y += fmaxf(acc, 0.f) * wvs[c];
    }
    y += __shfl_xor_sync(0xffffffffu, y, 1);
    y += __shfl_xor_sync(0xffffffffu, y, 2);
    if (q == 0) out[row] = y + z2[row >> 10] + bv[0];
}

// ---------------- launch ----------------------------------------------------
extern "C" void kernel_launch(void* const* d_in, const int* in_sizes, int n_in,
                              void* d_out, int out_size)
{
    const float* xin = (const float*)d_in[0];
    const int*   adj = (const int*)d_in[1];
    const float* w1  = (const float*)d_in[2];
    const float* as1 = (const float*)d_in[3];
    const float* ad1 = (const float*)d_in[4];
    const float* b1  = (const float*)d_in[5];
    const float* w2  = (const float*)d_in[6];
    const float* as2 = (const float*)d_in[7];
    const float* ad2 = (const float*)d_in[8];
    const float* b2  = (const float*)d_in[9];
    const float* w3  = (const float*)d_in[10];
    const float* as3 = (const float*)d_in[11];
    const float* ad3 = (const float*)d_in[12];
    const float* b3  = (const float*)d_in[13];
    const float* wn  = (const float*)d_in[14];
    const float* bn  = (const float*)d_in[15];
    const float* wg  = (const float*)d_in[16];
    const float* bg  = (const float*)d_in[17];
    const float* wv  = (const float*)d_in[18];
    const float* bv  = (const float*)d_in[19];
    float* out = (float*)d_out;

    float *bufA, *bufB, *sA, *EsA, *Es2A, *gsm, *z2p;
    float4* dpk;
    __nv_bfloat16 *hhi, *hlo;
    u32* bits;
    cudaGetSymbolAddress((void**)&bufA, g_bufA);
    cudaGetSymbolAddress((void**)&bufB, g_bufB);
    cudaGetSymbolAddress((void**)&sA,   g_sj);
    cudaGetSymbolAddress((void**)&EsA,  g_Esj);
    cudaGetSymbolAddress((void**)&Es2A, g_Es2);
    cudaGetSymbolAddress((void**)&dpk,  g_dpk);
    cudaGetSymbolAddress((void**)&hhi,  g_hThi);
    cudaGetSymbolAddress((void**)&hlo,  g_hTlo);
    cudaGetSymbolAddress((void**)&bits, g_bits);
    cudaGetSymbolAddress((void**)&gsm,  g_gsum);
    cudaGetSymbolAddress((void**)&z2p,  g_z2);

    const int M = BATCH * NT;
    const ull* bits64 = (const ull*)bits;

    pack_adj_kernel<<<M, 32>>>(adj, bits);

    // layer 1: 64 -> 4x64 (gemm + scores + split-transpose fused)
    gemm_fused<<<dim3(M / 128, 4), 256>>>(xin, w1, as1, ad1,
                                          sA, EsA, Es2A, dpk, hhi, hlo, 64);
    agg_mma_kernel<<<dim3(NT / 128, 4, BATCH), 256>>>(
        hhi, hlo, sA, EsA, Es2A, dpk, bits64, b1, bufB, 4);

    // layer 2: 4x64 -> 4x64
    gemm_fused<<<dim3(M / 128, 4), 256>>>(bufB, w2, as2, ad2,
                                          sA, EsA, Es2A, dpk, hhi, hlo, 256);
    agg_mma_kernel<<<dim3(NT / 128, 4, BATCH), 256>>>(
        hhi, hlo, sA, EsA, Es2A, dpk, bits64, b2, bufA, 4);

    // layer 3: 4x64 -> 64 (H=1)
    gemm_fused<<<dim3(M / 128, 1), 256>>>(bufA, w3, as3, ad3,
                                          sA, EsA, Es2A, dpk, hhi, hlo, 256);
    agg_mma_kernel<<<dim3(NT / 128, 1, BATCH), 256>>>(
        hhi, hlo, sA, EsA, Es2A, dpk, bits64, b3, bufB, 1);

    // readout
    gsum_kernel<<<BATCH, 256>>>(bufB, gsm);
    z2_kernel<<<BATCH, 64>>>(gsm, wg, bg, wv, z2p);
    final_kernel<<<M / 64, 256>>>(bufB, wn, bn, wv, bv, z2p, out);
}